// round 11
// baseline (speedup 1.0000x reference)
#include <cuda_runtime.h>
#include <math.h>

#define N_NODES 50000
#define N_EDGES 800000
#define E_TOT   (N_EDGES + N_NODES)   // with self loops = 850000
#define IN_C    768
#define HID     64
#define OUT_C   8
#define BN_EPS  1e-5f
#define NEG_SLOPE 0.2f
#define NKT     (IN_C / 64)           // 12 k-tiles

typedef unsigned long long u64;

// ---------------- device scratch (allocation-free) ----------------
__device__ float g_h[N_NODES * HID];        // current node features
__device__ float g_xw[N_NODES * HID];       // h @ W per conv
__device__ float g_asrc[N_NODES * 8];
__device__ float g_adst[N_NODES * 8];
__device__ float g_denom[N_NODES * 8];
__device__ float g_agg[N_NODES * HID];      // unnormalized aggregation

// ---------------- helpers ----------------
__device__ __forceinline__ float lrelu(float x) {
    return x > 0.f ? x : NEG_SLOPE * x;
}
__device__ __forceinline__ float elu1(float x) {
    return x > 0.f ? x : (expf(x) - 1.f);
}
__device__ __forceinline__ u64 pk2(float lo, float hi) {
    u64 r; asm("mov.b64 %0, {%1, %2};" : "=l"(r) : "f"(lo), "f"(hi)); return r;
}
__device__ __forceinline__ void fma2(u64& d, u64 a, u64 b) {
    asm("fma.rn.f32x2 %0, %1, %2, %0;" : "+l"(d) : "l"(a), "l"(b));
}
__device__ __forceinline__ float2 upk(u64 v) {
    float2 r; asm("mov.b64 {%0, %1}, %2;" : "=f"(r.x), "=f"(r.y) : "l"(v)); return r;
}
__device__ __forceinline__ void atomicAddF4(float4* p, float4 v) {
#if __CUDA_ARCH__ >= 900
    atomicAdd(p, v);
#else
    atomicAdd(&p->x, v.x); atomicAdd(&p->y, v.y);
    atomicAdd(&p->z, v.z); atomicAdd(&p->w, v.w);
#endif
}
__device__ __forceinline__ void edge_decode(const int* __restrict__ ei, int e,
                                            int& src, int& dst) {
    if (e < N_EDGES) { src = ei[e]; dst = ei[N_EDGES + e]; }
    else             { src = dst = e - N_EDGES; }
}

// ---------------- K1: h = elu(bn1(x @ proj_W + proj_b)) ----------------
// 64x64 tile, 128 threads, 8x4 register block, FFMA2 inner loop.
// Register double-buffering: prefetch k-tile t+1 (LDG) while computing tile t.
__global__ __launch_bounds__(128) void k_gemm_in(
    const float* __restrict__ x, const float* __restrict__ W,
    const float* __restrict__ pb,
    const float* __restrict__ bg, const float* __restrict__ bb,
    const float* __restrict__ bm, const float* __restrict__ bv)
{
    __shared__ float xs[64][65];
    __shared__ float ws[64][64];
    const int tid = threadIdx.x;
    const int r0 = blockIdx.x * 64;
    const int cg = tid & 15;      // 16 col groups of 4
    const int rg = tid >> 4;      // 8 row groups of 8
    // per-thread load coordinates (same for every tile)
    const int lrow = tid >> 4;            // rows loaded: lrow, lrow+8*i pattern below
    u64 acc01[8], acc23[8];
#pragma unroll
    for (int i = 0; i < 8; i++) { acc01[i] = 0ull; acc23[i] = 0ull; }

    float4 xr[8], wr[8];
    // prefetch tile 0
#pragma unroll
    for (int i = 0; i < 8; i++) {
        int s = tid + i * 128;
        int row = s >> 4, c4 = (s & 15) * 4;
        int gr = r0 + row;
        xr[i] = (gr < N_NODES) ? *(const float4*)&x[(size_t)gr * IN_C + 0 + c4]
                               : make_float4(0.f, 0.f, 0.f, 0.f);
        wr[i] = *(const float4*)&W[(size_t)(0 + row) * HID + c4];
    }

    for (int kt = 0; kt < NKT; kt++) {
        // store prefetched tile to smem
#pragma unroll
        for (int i = 0; i < 8; i++) {
            int s = tid + i * 128;
            int row = s >> 4, c4 = (s & 15) * 4;
            xs[row][c4+0] = xr[i].x; xs[row][c4+1] = xr[i].y;
            xs[row][c4+2] = xr[i].z; xs[row][c4+3] = xr[i].w;
            *(float4*)&ws[row][c4] = wr[i];
        }
        __syncthreads();
        // issue prefetch for next tile (overlaps with compute below)
        if (kt + 1 < NKT) {
            int kc = (kt + 1) * 64;
#pragma unroll
            for (int i = 0; i < 8; i++) {
                int s = tid + i * 128;
                int row = s >> 4, c4 = (s & 15) * 4;
                int gr = r0 + row;
                xr[i] = (gr < N_NODES)
                      ? *(const float4*)&x[(size_t)gr * IN_C + kc + c4]
                      : make_float4(0.f, 0.f, 0.f, 0.f);
                wr[i] = *(const float4*)&W[(size_t)(kc + row) * HID + c4];
            }
        }
#pragma unroll 8
        for (int k = 0; k < 64; k++) {
            float4 w = *(float4*)&ws[k][cg * 4];
            u64 w01 = pk2(w.x, w.y);
            u64 w23 = pk2(w.z, w.w);
#pragma unroll
            for (int i = 0; i < 8; i++) {
                float xv = xs[rg * 8 + i][k];
                u64 xx = pk2(xv, xv);
                fma2(acc01[i], xx, w01);
                fma2(acc23[i], xx, w23);
            }
        }
        __syncthreads();
    }
    (void)lrow;
    const int c0 = cg * 4;
    float sc[4], of[4];
#pragma unroll
    for (int j = 0; j < 4; j++) {
        int c = c0 + j;
        float s = bg[c] * rsqrtf(bv[c] + BN_EPS);
        sc[j] = s;
        of[j] = (pb[c] - bm[c]) * s + bb[c];
    }
#pragma unroll
    for (int i = 0; i < 8; i++) {
        int gr = r0 + rg * 8 + i;
        if (gr < N_NODES) {
            float2 a01 = upk(acc01[i]);
            float2 a23 = upk(acc23[i]);
            float4 o;
            o.x = elu1(a01.x * sc[0] + of[0]);
            o.y = elu1(a01.y * sc[1] + of[1]);
            o.z = elu1(a23.x * sc[2] + of[2]);
            o.w = elu1(a23.y * sc[3] + of[3]);
            *(float4*)&g_h[(size_t)gr * HID + c0] = o;
        }
    }
}

// ---------------- K2: xw = g_h @ W (64x64), conv1 ----------------
__global__ __launch_bounds__(128) void k_gemm64(const float* __restrict__ W)
{
    __shared__ float xs[64][65];
    __shared__ float ws[64][64];
    const int tid = threadIdx.x;
    const int r0 = blockIdx.x * 64;
    const int cg = tid & 15;
    const int rg = tid >> 4;
    u64 acc01[8], acc23[8];
#pragma unroll
    for (int i = 0; i < 8; i++) { acc01[i] = 0ull; acc23[i] = 0ull; }

#pragma unroll
    for (int i = 0; i < 8; i++) {
        int s = tid + i * 128;
        int row = s >> 4, c4 = (s & 15) * 4;
        float4 val = make_float4(0.f, 0.f, 0.f, 0.f);
        int gr = r0 + row;
        if (gr < N_NODES)
            val = *(const float4*)&g_h[(size_t)gr * HID + c4];
        xs[row][c4+0] = val.x; xs[row][c4+1] = val.y;
        xs[row][c4+2] = val.z; xs[row][c4+3] = val.w;
        *(float4*)&ws[row][c4] = *(const float4*)&W[(size_t)row * HID + c4];
    }
    __syncthreads();
#pragma unroll 8
    for (int k = 0; k < 64; k++) {
        float4 w = *(float4*)&ws[k][cg * 4];
        u64 w01 = pk2(w.x, w.y);
        u64 w23 = pk2(w.z, w.w);
#pragma unroll
        for (int i = 0; i < 8; i++) {
            float xv = xs[rg * 8 + i][k];
            u64 xx = pk2(xv, xv);
            fma2(acc01[i], xx, w01);
            fma2(acc23[i], xx, w23);
        }
    }
    const int c0 = cg * 4;
#pragma unroll
    for (int i = 0; i < 8; i++) {
        int gr = r0 + rg * 8 + i;
        if (gr < N_NODES) {
            float2 a01 = upk(acc01[i]);
            float2 a23 = upk(acc23[i]);
            *(float4*)&g_xw[(size_t)gr * HID + c0] =
                make_float4(a01.x, a01.y, a23.x, a23.y);
        }
    }
}

// ---- K2b: conv2 GEMM with FUSED conv1-post in the load stage -----------
// h = elu(bn2(agg/denom + b1) + h_old); writes g_h (conv2 identity) and
// computes xw = h @ W2. Replaces k_post<8> + k_gemm64.
__global__ __launch_bounds__(128) void k_gemm64_post(
    const float* __restrict__ W,
    const float* __restrict__ bias,
    const float* __restrict__ bg, const float* __restrict__ bb,
    const float* __restrict__ bm, const float* __restrict__ bv)
{
    __shared__ float xs[64][65];
    __shared__ float ws[64][64];
    const int tid = threadIdx.x;
    const int r0 = blockIdx.x * 64;
    const int cg = tid & 15;
    const int rg = tid >> 4;
    u64 acc01[8], acc23[8];
#pragma unroll
    for (int i = 0; i < 8; i++) { acc01[i] = 0ull; acc23[i] = 0ull; }

#pragma unroll
    for (int i = 0; i < 8; i++) {
        int s = tid + i * 128;
        int row = s >> 4, c4 = (s & 15) * 4;
        int gr = r0 + row;
        float4 o = make_float4(0.f, 0.f, 0.f, 0.f);
        if (gr < N_NODES) {
            float4 a  = *(const float4*)&g_agg[(size_t)gr * HID + c4];
            float4 ho = *(const float4*)&g_h[(size_t)gr * HID + c4];
            float inv = 1.f / g_denom[gr * 8 + (c4 >> 3)];
            float av[4] = { a.x * inv, a.y * inv, a.z * inv, a.w * inv };
            float hv[4] = { ho.x, ho.y, ho.z, ho.w };
            float ov[4];
#pragma unroll
            for (int jj = 0; jj < 4; jj++) {
                int c = c4 + jj;
                float sfac = bg[c] * rsqrtf(bv[c] + BN_EPS);
                float t = (av[jj] + bias[c] - bm[c]) * sfac + bb[c] + hv[jj];
                ov[jj] = elu1(t);
            }
            o = make_float4(ov[0], ov[1], ov[2], ov[3]);
            *(float4*)&g_h[(size_t)gr * HID + c4] = o;   // conv2 identity
        }
        xs[row][c4+0] = o.x; xs[row][c4+1] = o.y;
        xs[row][c4+2] = o.z; xs[row][c4+3] = o.w;
        *(float4*)&ws[row][c4] = *(const float4*)&W[(size_t)row * HID + c4];
    }
    __syncthreads();
#pragma unroll 8
    for (int k = 0; k < 64; k++) {
        float4 w = *(float4*)&ws[k][cg * 4];
        u64 w01 = pk2(w.x, w.y);
        u64 w23 = pk2(w.z, w.w);
#pragma unroll
        for (int i = 0; i < 8; i++) {
            float xv = xs[rg * 8 + i][k];
            u64 xx = pk2(xv, xv);
            fma2(acc01[i], xx, w01);
            fma2(acc23[i], xx, w23);
        }
    }
    const int c0 = cg * 4;
#pragma unroll
    for (int i = 0; i < 8; i++) {
        int gr = r0 + rg * 8 + i;
        if (gr < N_NODES) {
            float2 a01 = upk(acc01[i]);
            float2 a23 = upk(acc23[i]);
            *(float4*)&g_xw[(size_t)gr * HID + c0] =
                make_float4(a01.x, a01.y, a23.x, a23.y);
        }
    }
}

// ---------------- K3: per-node attention logits + accumulator zeroing ----
template<int H, int C>
__global__ void k_att(const float* __restrict__ att_s,
                      const float* __restrict__ att_d)
{
    int warp = (blockIdx.x * blockDim.x + threadIdx.x) >> 5;
    int lane = threadIdx.x & 31;
    if (warp >= N_NODES) return;

    // zero accumulators for this node (consumed by k_edge next)
    *(float2*)&g_agg[(size_t)warp * HID + lane * 2] = make_float2(0.f, 0.f);
    if (H == 8) {
        if (lane < 8) g_denom[warp * 8 + lane] = 0.f;
    } else {
        if (lane == 0) g_denom[warp] = 0.f;
    }

    float2 xv = *(const float2*)&g_xw[warp * HID + lane * 2];
    float2 as = *(const float2*)&att_s[lane * 2];
    float2 ad = *(const float2*)&att_d[lane * 2];
    float ps = xv.x * as.x + xv.y * as.y;
    float pd = xv.x * ad.x + xv.y * ad.y;
    const int G = C / 2;   // lanes per head
#pragma unroll
    for (int off = G >> 1; off > 0; off >>= 1) {
        ps += __shfl_xor_sync(0xffffffffu, ps, off);
        pd += __shfl_xor_sync(0xffffffffu, pd, off);
    }
    if ((lane & (G - 1)) == 0) {
        int h = lane / G;
        g_asrc[warp * H + h] = ps;
        g_adst[warp * H + h] = pd;
    }
}

// ---------------- K5: FUSED edge pass ----------------
// 8 threads per edge; lane j handles head j (H=8) / features j*8..j*8+7.
template<int H>
__global__ void k_edge(const int* __restrict__ ei)
{
    int t = blockIdx.x * blockDim.x + threadIdx.x;
    int j = t & 7;
    int e = t >> 3;
    if (e >= E_TOT) return;
    int src, dst;
    edge_decode(ei, e, src, dst);
    float ex;
    if (H == 8) {
        float a = g_asrc[src * 8 + j] + g_adst[dst * 8 + j];
        ex = expf(lrelu(a));
        atomicAdd(&g_denom[dst * 8 + j], ex);
    } else {
        float a = g_asrc[src] + g_adst[dst];
        ex = expf(lrelu(a));
        if (j == 0) atomicAdd(&g_denom[dst], ex);
    }
    const float4* xp = (const float4*)&g_xw[src * HID + j * 8];
    float4 a = xp[0], b = xp[1];
    a.x *= ex; a.y *= ex; a.z *= ex; a.w *= ex;
    b.x *= ex; b.y *= ex; b.z *= ex; b.w *= ex;
    atomicAddF4((float4*)&g_agg[dst * HID + j * 8], a);
    atomicAddF4((float4*)&g_agg[dst * HID + j * 8 + 4], b);
}

// ---------------- K7: classifier with FUSED conv2-post -------------------
// h_final = elu(bn3(agg/denom + b2) + h_old) computed in the load stage,
// then out = h_final @ cls_W + cls_b. Replaces k_post<1> + k_cls.
__global__ __launch_bounds__(128) void k_cls_post(
    const float* __restrict__ W, const float* __restrict__ biasc,
    const float* __restrict__ bias2,
    const float* __restrict__ bg, const float* __restrict__ bb,
    const float* __restrict__ bm, const float* __restrict__ bv,
    float* __restrict__ out)
{
    __shared__ float hs[128][65];
    __shared__ float ws[64][8];
    const int tid = threadIdx.x;
    const int n0 = blockIdx.x * 128;
#pragma unroll
    for (int i = 0; i < 4; i++) {
        int s = tid + i * 128;
        ws[s >> 3][s & 7] = W[s];
    }
#pragma unroll
    for (int i = 0; i < 16; i++) {
        int s = tid + i * 128;            // float4 slot
        int row = s >> 4, c4 = (s & 15) * 4;
        int node = n0 + row;
        float4 o = make_float4(0.f, 0.f, 0.f, 0.f);
        if (node < N_NODES) {
            float4 a  = *(const float4*)&g_agg[(size_t)node * HID + c4];
            float4 ho = *(const float4*)&g_h[(size_t)node * HID + c4];
            float inv = 1.f / g_denom[node];          // H=1
            float av[4] = { a.x * inv, a.y * inv, a.z * inv, a.w * inv };
            float hv[4] = { ho.x, ho.y, ho.z, ho.w };
            float ov[4];
#pragma unroll
            for (int jj = 0; jj < 4; jj++) {
                int c = c4 + jj;
                float sfac = bg[c] * rsqrtf(bv[c] + BN_EPS);
                float t = (av[jj] + bias2[c] - bm[c]) * sfac + bb[c] + hv[jj];
                ov[jj] = elu1(t);
            }
            o = make_float4(ov[0], ov[1], ov[2], ov[3]);
        }
        hs[row][c4+0] = o.x; hs[row][c4+1] = o.y;
        hs[row][c4+2] = o.z; hs[row][c4+3] = o.w;
    }
    __syncthreads();
    if (n0 + tid >= N_NODES) return;
    float acc[8];
#pragma unroll
    for (int jj = 0; jj < 8; jj++) acc[jj] = biasc[jj];
#pragma unroll 8
    for (int k = 0; k < 64; k++) {
        float xv = hs[tid][k];
        float4 w0 = *(float4*)&ws[k][0];
        float4 w1 = *(float4*)&ws[k][4];
        acc[0] += xv * w0.x; acc[1] += xv * w0.y;
        acc[2] += xv * w0.z; acc[3] += xv * w0.w;
        acc[4] += xv * w1.x; acc[5] += xv * w1.y;
        acc[6] += xv * w1.z; acc[7] += xv * w1.w;
    }
    float* op = &out[(size_t)(n0 + tid) * 8];
    *(float4*)&op[0] = make_float4(acc[0], acc[1], acc[2], acc[3]);
    *(float4*)&op[4] = make_float4(acc[4], acc[5], acc[6], acc[7]);
}

// ---------------- launch ----------------
extern "C" void kernel_launch(void* const* d_in, const int* in_sizes, int n_in,
                              void* d_out, int out_size)
{
    const float* x        = (const float*)d_in[0];
    const int*   ei       = (const int*)  d_in[1];
    const float* proj_W   = (const float*)d_in[2];
    const float* proj_b   = (const float*)d_in[3];
    const float* bn1_g    = (const float*)d_in[4];
    const float* bn1_b    = (const float*)d_in[5];
    const float* bn1_m    = (const float*)d_in[6];
    const float* bn1_v    = (const float*)d_in[7];
    const float* bn2_g    = (const float*)d_in[8];
    const float* bn2_b    = (const float*)d_in[9];
    const float* bn2_m    = (const float*)d_in[10];
    const float* bn2_v    = (const float*)d_in[11];
    const float* bn3_g    = (const float*)d_in[12];
    const float* bn3_b    = (const float*)d_in[13];
    const float* bn3_m    = (const float*)d_in[14];
    const float* bn3_v    = (const float*)d_in[15];
    const float* W1       = (const float*)d_in[16];
    const float* att_src1 = (const float*)d_in[17];
    const float* att_dst1 = (const float*)d_in[18];
    const float* b1       = (const float*)d_in[19];
    const float* W2       = (const float*)d_in[20];
    const float* att_src2 = (const float*)d_in[21];
    const float* att_dst2 = (const float*)d_in[22];
    const float* b2       = (const float*)d_in[23];
    const float* cls_W    = (const float*)d_in[24];
    const float* cls_b    = (const float*)d_in[25];
    float* out = (float*)d_out;

    const int GEMM_BLOCKS = (N_NODES + 63) / 64;              // 782
    const int EDGE_BLOCKS = (E_TOT * 8 + 255) / 256;          // 26563
    const int ATT_BLOCKS  = (N_NODES + 7) / 8;                // 6250

    // projection + bn1 + elu
    k_gemm_in<<<GEMM_BLOCKS, 128>>>(x, proj_W, proj_b, bn1_g, bn1_b, bn1_m, bn1_v);

    // ---- conv1 (H=8, C=8) ----
    k_gemm64<<<GEMM_BLOCKS, 128>>>(W1);
    k_att<8, 8><<<ATT_BLOCKS, 256>>>(att_src1, att_dst1);   // also zeroes agg/denom
    k_edge<8><<<EDGE_BLOCKS, 256>>>(ei);

    // ---- conv2 (H=1, C=64); conv1-post fused into its GEMM ----
    k_gemm64_post<<<GEMM_BLOCKS, 128>>>(W2, b1, bn2_g, bn2_b, bn2_m, bn2_v);
    k_att<1, 64><<<ATT_BLOCKS, 256>>>(att_src2, att_dst2);  // also zeroes agg/denom
    k_edge<1><<<EDGE_BLOCKS, 256>>>(ei);

    // classifier; conv2-post fused into its load stage
    k_cls_post<<<(N_NODES + 127) / 128, 128>>>(cls_W, cls_b, b2,
                                               bn3_g, bn3_b, bn3_m, bn3_v, out);
}

// round 13
// speedup vs baseline: 1.3247x; 1.3247x over previous
#include <cuda_runtime.h>
#include <math.h>
#include <stdint.h>

#define N_NODES 50000
#define N_EDGES 800000
#define E_TOT   (N_EDGES + N_NODES)   // with self loops = 850000
#define IN_C    768
#define HID     64
#define OUT_C   8
#define BN_EPS  1e-5f
#define NEG_SLOPE 0.2f
#define NKT     (IN_C / 64)           // 12 k-tiles

typedef unsigned long long u64;

// ---------------- device scratch (allocation-free) ----------------
__device__ float g_h[N_NODES * HID];        // current node features
__device__ float g_xw[N_NODES * HID];       // h @ W per conv
__device__ float g_asrc[N_NODES * 8];
__device__ float g_adst[N_NODES * 8];
__device__ float g_denom[N_NODES * 8];
__device__ float g_agg[N_NODES * HID];      // unnormalized aggregation

// ---------------- helpers ----------------
__device__ __forceinline__ float lrelu(float x) {
    return x > 0.f ? x : NEG_SLOPE * x;
}
__device__ __forceinline__ float elu1(float x) {
    return x > 0.f ? x : (expf(x) - 1.f);
}
__device__ __forceinline__ u64 pk2(float lo, float hi) {
    u64 r; asm("mov.b64 %0, {%1, %2};" : "=l"(r) : "f"(lo), "f"(hi)); return r;
}
__device__ __forceinline__ void fma2(u64& d, u64 a, u64 b) {
    asm("fma.rn.f32x2 %0, %1, %2, %0;" : "+l"(d) : "l"(a), "l"(b));
}
__device__ __forceinline__ float2 upk(u64 v) {
    float2 r; asm("mov.b64 {%0, %1}, %2;" : "=f"(r.x), "=f"(r.y) : "l"(v)); return r;
}
__device__ __forceinline__ void atomicAddF4(float4* p, float4 v) {
#if __CUDA_ARCH__ >= 900
    atomicAdd(p, v);
#else
    atomicAdd(&p->x, v.x); atomicAdd(&p->y, v.y);
    atomicAdd(&p->z, v.z); atomicAdd(&p->w, v.w);
#endif
}
__device__ __forceinline__ void edge_decode(const int* __restrict__ ei, int e,
                                            int& src, int& dst) {
    if (e < N_EDGES) { src = ei[e]; dst = ei[N_EDGES + e]; }
    else             { src = dst = e - N_EDGES; }
}
__device__ __forceinline__ void cpa16(uint32_t dst, const void* src, int sz) {
    asm volatile("cp.async.cg.shared.global [%0], [%1], 16, %2;"
                 :: "r"(dst), "l"(src), "r"(sz));
}
__device__ __forceinline__ void cpa_commit() {
    asm volatile("cp.async.commit_group;");
}
template<int N>
__device__ __forceinline__ void cpa_wait() {
    asm volatile("cp.async.wait_group %0;" :: "n"(N));
}

// ---------------- K1: h = elu(bn1(x @ proj_W + proj_b)) ----------------
// 64x64 tile, 128 threads, 8x4 register block, FFMA2 inner loop.
// cp.async double-buffered x tiles. Race-free ordering: a stage is written
// only in the iteration AFTER the loop-end barrier that retires its readers.
__global__ __launch_bounds__(128) void k_gemm_in(
    const float* __restrict__ x, const float* __restrict__ W,
    const float* __restrict__ pb,
    const float* __restrict__ bg, const float* __restrict__ bb,
    const float* __restrict__ bm, const float* __restrict__ bv)
{
    __shared__ float xs[2][64][64];   // 32 KB; 256B rows, 16B-aligned for cp.async
    __shared__ float ws[64][64];      // 16 KB
    const int tid = threadIdx.x;
    const int r0 = blockIdx.x * 64;
    const int cg = tid & 15;      // 16 col groups of 4
    const int rg = tid >> 4;      // 8 row groups of 8
    const uint32_t xs_base = (uint32_t)__cvta_generic_to_shared(&xs[0][0][0]);

    u64 acc01[8], acc23[8];
#pragma unroll
    for (int i = 0; i < 8; i++) { acc01[i] = 0ull; acc23[i] = 0ull; }

    // prologue: async-load x tile 0 into stage 0; W tile 0 into registers
#pragma unroll
    for (int i = 0; i < 8; i++) {
        int s = tid + i * 128;
        int row = s >> 4, c4 = (s & 15) * 4;
        int gr = r0 + row;
        const float* src = &x[(size_t)(gr < N_NODES ? gr : 0) * IN_C + c4];
        cpa16(xs_base + (uint32_t)((row * 64 + c4) * 4), src,
              gr < N_NODES ? 16 : 0);
    }
    cpa_commit();
    float4 wr[8];
#pragma unroll
    for (int i = 0; i < 8; i++) {
        int s = tid + i * 128;
        int row = s >> 4, c4 = (s & 15) * 4;
        wr[i] = *(const float4*)&W[(size_t)row * HID + c4];
    }

    for (int kt = 0; kt < NKT; kt++) {
        const int cur = kt & 1;
        // 1. stash this tile's W regs into smem (prev compute retired by
        //    loop-end barrier; at kt=0 nothing to retire)
#pragma unroll
        for (int i = 0; i < 8; i++) {
            int s = tid + i * 128;
            int row = s >> 4, c4 = (s & 15) * 4;
            *(float4*)&ws[row][c4] = wr[i];
        }
        // 2. issue async-load of tile kt+1 into the other stage
        //    (safe: its last readers were retired by the loop-end barrier)
        if (kt + 1 < NKT) {
            int kc = (kt + 1) * 64;
#pragma unroll
            for (int i = 0; i < 8; i++) {
                int s = tid + i * 128;
                int row = s >> 4, c4 = (s & 15) * 4;
                int gr = r0 + row;
                const float* src = &x[(size_t)(gr < N_NODES ? gr : 0) * IN_C + kc + c4];
                cpa16(xs_base + (uint32_t)(((cur ^ 1) * 4096 + row * 64 + c4) * 4),
                      src, gr < N_NODES ? 16 : 0);
            }
            cpa_commit();
        }
        // 3. tile kt's copies complete (kt+1's group may stay in flight)
        if (kt + 1 < NKT) cpa_wait<1>(); else cpa_wait<0>();
        __syncthreads();
        // 4. prefetch next W tile into regs (overlaps with compute below)
        if (kt + 1 < NKT) {
            int kc = (kt + 1) * 64;
#pragma unroll
            for (int i = 0; i < 8; i++) {
                int s = tid + i * 128;
                int row = s >> 4, c4 = (s & 15) * 4;
                wr[i] = *(const float4*)&W[(size_t)(kc + row) * HID + c4];
            }
        }
#pragma unroll 8
        for (int k = 0; k < 64; k++) {
            float4 w = *(float4*)&ws[k][cg * 4];
            u64 w01 = pk2(w.x, w.y);
            u64 w23 = pk2(w.z, w.w);
#pragma unroll
            for (int i = 0; i < 8; i++) {
                float xv = xs[cur][rg * 8 + i][k];
                u64 xx = pk2(xv, xv);
                fma2(acc01[i], xx, w01);
                fma2(acc23[i], xx, w23);
            }
        }
        // 5. retire this iteration's readers of xs[cur] and ws before the
        //    next iteration overwrites ws / issues into stage cur
        __syncthreads();
    }
    const int c0 = cg * 4;
    float sc[4], of[4];
#pragma unroll
    for (int j = 0; j < 4; j++) {
        int c = c0 + j;
        float s = bg[c] * rsqrtf(bv[c] + BN_EPS);
        sc[j] = s;
        of[j] = (pb[c] - bm[c]) * s + bb[c];
    }
#pragma unroll
    for (int i = 0; i < 8; i++) {
        int gr = r0 + rg * 8 + i;
        if (gr < N_NODES) {
            float2 a01 = upk(acc01[i]);
            float2 a23 = upk(acc23[i]);
            float4 o;
            o.x = elu1(a01.x * sc[0] + of[0]);
            o.y = elu1(a01.y * sc[1] + of[1]);
            o.z = elu1(a23.x * sc[2] + of[2]);
            o.w = elu1(a23.y * sc[3] + of[3]);
            *(float4*)&g_h[(size_t)gr * HID + c0] = o;
        }
    }
}

// ---------------- K2: xw = g_h @ W (64x64) ----------------
__global__ __launch_bounds__(128) void k_gemm64(const float* __restrict__ W)
{
    __shared__ float xs[64][65];
    __shared__ float ws[64][64];
    const int tid = threadIdx.x;
    const int r0 = blockIdx.x * 64;
    const int cg = tid & 15;
    const int rg = tid >> 4;
    u64 acc01[8], acc23[8];
#pragma unroll
    for (int i = 0; i < 8; i++) { acc01[i] = 0ull; acc23[i] = 0ull; }

#pragma unroll
    for (int i = 0; i < 8; i++) {
        int s = tid + i * 128;
        int row = s >> 4, c4 = (s & 15) * 4;
        float4 val = make_float4(0.f, 0.f, 0.f, 0.f);
        int gr = r0 + row;
        if (gr < N_NODES)
            val = *(const float4*)&g_h[(size_t)gr * HID + c4];
        xs[row][c4+0] = val.x; xs[row][c4+1] = val.y;
        xs[row][c4+2] = val.z; xs[row][c4+3] = val.w;
        *(float4*)&ws[row][c4] = *(const float4*)&W[(size_t)row * HID + c4];
    }
    __syncthreads();
#pragma unroll 8
    for (int k = 0; k < 64; k++) {
        float4 w = *(float4*)&ws[k][cg * 4];
        u64 w01 = pk2(w.x, w.y);
        u64 w23 = pk2(w.z, w.w);
#pragma unroll
        for (int i = 0; i < 8; i++) {
            float xv = xs[rg * 8 + i][k];
            u64 xx = pk2(xv, xv);
            fma2(acc01[i], xx, w01);
            fma2(acc23[i], xx, w23);
        }
    }
    const int c0 = cg * 4;
#pragma unroll
    for (int i = 0; i < 8; i++) {
        int gr = r0 + rg * 8 + i;
        if (gr < N_NODES) {
            float2 a01 = upk(acc01[i]);
            float2 a23 = upk(acc23[i]);
            *(float4*)&g_xw[(size_t)gr * HID + c0] =
                make_float4(a01.x, a01.y, a23.x, a23.y);
        }
    }
}

// ---------------- K3: per-node attention logits + accumulator zeroing ----
template<int H, int C>
__global__ void k_att(const float* __restrict__ att_s,
                      const float* __restrict__ att_d)
{
    int warp = (blockIdx.x * blockDim.x + threadIdx.x) >> 5;
    int lane = threadIdx.x & 31;
    if (warp >= N_NODES) return;

    // zero accumulators for this node (consumed by k_edge next)
    *(float2*)&g_agg[(size_t)warp * HID + lane * 2] = make_float2(0.f, 0.f);
    if (H == 8) {
        if (lane < 8) g_denom[warp * 8 + lane] = 0.f;
    } else {
        if (lane == 0) g_denom[warp] = 0.f;
    }

    float2 xv = *(const float2*)&g_xw[warp * HID + lane * 2];
    float2 as = *(const float2*)&att_s[lane * 2];
    float2 ad = *(const float2*)&att_d[lane * 2];
    float ps = xv.x * as.x + xv.y * as.y;
    float pd = xv.x * ad.x + xv.y * ad.y;
    const int G = C / 2;   // lanes per head
#pragma unroll
    for (int off = G >> 1; off > 0; off >>= 1) {
        ps += __shfl_xor_sync(0xffffffffu, ps, off);
        pd += __shfl_xor_sync(0xffffffffu, pd, off);
    }
    if ((lane & (G - 1)) == 0) {
        int h = lane / G;
        g_asrc[warp * H + h] = ps;
        g_adst[warp * H + h] = pd;
    }
}

// ---------------- K5: FUSED edge pass ----------------
// 8 threads per edge; lane j handles head j (H=8) / features j*8..j*8+7.
template<int H>
__global__ void k_edge(const int* __restrict__ ei)
{
    int t = blockIdx.x * blockDim.x + threadIdx.x;
    int j = t & 7;
    int e = t >> 3;
    if (e >= E_TOT) return;
    int src, dst;
    edge_decode(ei, e, src, dst);
    float ex;
    if (H == 8) {
        float a = g_asrc[src * 8 + j] + g_adst[dst * 8 + j];
        ex = expf(lrelu(a));
        atomicAdd(&g_denom[dst * 8 + j], ex);
    } else {
        float a = g_asrc[src] + g_adst[dst];
        ex = expf(lrelu(a));
        if (j == 0) atomicAdd(&g_denom[dst], ex);
    }
    const float4* xp = (const float4*)&g_xw[src * HID + j * 8];
    float4 a = xp[0], b = xp[1];
    a.x *= ex; a.y *= ex; a.z *= ex; a.w *= ex;
    b.x *= ex; b.y *= ex; b.z *= ex; b.w *= ex;
    atomicAddF4((float4*)&g_agg[dst * HID + j * 8], a);
    atomicAddF4((float4*)&g_agg[dst * HID + j * 8 + 4], b);
}

// ---------------- K6: h = elu(bn(agg/denom + bias) + h_old) ----------------
template<int H>
__global__ void k_post(const float* __restrict__ bias,
                       const float* __restrict__ bg, const float* __restrict__ bb,
                       const float* __restrict__ bm, const float* __restrict__ bv)
{
    int i4 = blockIdx.x * blockDim.x + threadIdx.x;
    if (i4 >= N_NODES * (HID / 4)) return;
    int node = i4 >> 4;
    int c0 = (i4 & 15) * 4;
    // head is constant across the 4 cols of this float4 (c0 % 8 in {0,4})
    float dn = (H == 8) ? g_denom[node * 8 + (c0 >> 3)] : g_denom[node];
    float inv = 1.f / dn;
    float4 a  = *(float4*)&g_agg[(size_t)i4 * 4];
    float4 ho = *(float4*)&g_h[(size_t)i4 * 4];
    float av[4] = { a.x * inv, a.y * inv, a.z * inv, a.w * inv };
    float hv[4] = { ho.x, ho.y, ho.z, ho.w };
    float ov[4];
#pragma unroll
    for (int jj = 0; jj < 4; jj++) {
        int c = c0 + jj;
        float s = bg[c] * rsqrtf(bv[c] + BN_EPS);
        float t = (av[jj] + bias[c] - bm[c]) * s + bb[c] + hv[jj];
        ov[jj] = elu1(t);
    }
    *(float4*)&g_h[(size_t)i4 * 4] = make_float4(ov[0], ov[1], ov[2], ov[3]);
}

// ---------------- K7: classifier out = h @ cls_W + cls_b ----------------
__global__ __launch_bounds__(128) void k_cls(const float* __restrict__ W,
                                             const float* __restrict__ bias,
                                             float* __restrict__ out)
{
    __shared__ float hs[128][65];
    __shared__ float ws[64][8];
    const int tid = threadIdx.x;
    const int n0 = blockIdx.x * 128;
#pragma unroll
    for (int i = 0; i < 4; i++) {
        int s = tid + i * 128;
        ws[s >> 3][s & 7] = W[s];
    }
#pragma unroll
    for (int i = 0; i < 16; i++) {
        int s = tid + i * 128;            // float4 slot
        int row = s >> 4, c4 = (s & 15) * 4;
        float4 val = make_float4(0.f, 0.f, 0.f, 0.f);
        if (n0 + row < N_NODES)
            val = *(const float4*)&g_h[(size_t)(n0 + row) * HID + c4];
        hs[row][c4+0] = val.x; hs[row][c4+1] = val.y;
        hs[row][c4+2] = val.z; hs[row][c4+3] = val.w;
    }
    __syncthreads();
    if (n0 + tid >= N_NODES) return;
    float acc[8];
#pragma unroll
    for (int jj = 0; jj < 8; jj++) acc[jj] = bias[jj];
#pragma unroll 8
    for (int k = 0; k < 64; k++) {
        float xv = hs[tid][k];
        float4 w0 = *(float4*)&ws[k][0];
        float4 w1 = *(float4*)&ws[k][4];
        acc[0] += xv * w0.x; acc[1] += xv * w0.y;
        acc[2] += xv * w0.z; acc[3] += xv * w0.w;
        acc[4] += xv * w1.x; acc[5] += xv * w1.y;
        acc[6] += xv * w1.z; acc[7] += xv * w1.w;
    }
    float* op = &out[(size_t)(n0 + tid) * 8];
    *(float4*)&op[0] = make_float4(acc[0], acc[1], acc[2], acc[3]);
    *(float4*)&op[4] = make_float4(acc[4], acc[5], acc[6], acc[7]);
}

// ---------------- launch ----------------
extern "C" void kernel_launch(void* const* d_in, const int* in_sizes, int n_in,
                              void* d_out, int out_size)
{
    const float* x        = (const float*)d_in[0];
    const int*   ei       = (const int*)  d_in[1];
    const float* proj_W   = (const float*)d_in[2];
    const float* proj_b   = (const float*)d_in[3];
    const float* bn1_g    = (const float*)d_in[4];
    const float* bn1_b    = (const float*)d_in[5];
    const float* bn1_m    = (const float*)d_in[6];
    const float* bn1_v    = (const float*)d_in[7];
    const float* bn2_g    = (const float*)d_in[8];
    const float* bn2_b    = (const float*)d_in[9];
    const float* bn2_m    = (const float*)d_in[10];
    const float* bn2_v    = (const float*)d_in[11];
    const float* bn3_g    = (const float*)d_in[12];
    const float* bn3_b    = (const float*)d_in[13];
    const float* bn3_m    = (const float*)d_in[14];
    const float* bn3_v    = (const float*)d_in[15];
    const float* W1       = (const float*)d_in[16];
    const float* att_src1 = (const float*)d_in[17];
    const float* att_dst1 = (const float*)d_in[18];
    const float* b1       = (const float*)d_in[19];
    const float* W2       = (const float*)d_in[20];
    const float* att_src2 = (const float*)d_in[21];
    const float* att_dst2 = (const float*)d_in[22];
    const float* b2       = (const float*)d_in[23];
    const float* cls_W    = (const float*)d_in[24];
    const float* cls_b    = (const float*)d_in[25];
    float* out = (float*)d_out;

    const int GEMM_BLOCKS = (N_NODES + 63) / 64;              // 782
    const int EDGE_BLOCKS = (E_TOT * 8 + 255) / 256;          // 26563
    const int POST_BLOCKS = (N_NODES * (HID/4) + 255) / 256;  // 3125
    const int ATT_BLOCKS  = (N_NODES + 7) / 8;                // 6250

    // projection + bn1 + elu
    k_gemm_in<<<GEMM_BLOCKS, 128>>>(x, proj_W, proj_b, bn1_g, bn1_b, bn1_m, bn1_v);

    // ---- conv1 (H=8, C=8) ----
    k_gemm64<<<GEMM_BLOCKS, 128>>>(W1);
    k_att<8, 8><<<ATT_BLOCKS, 256>>>(att_src1, att_dst1);   // also zeroes agg/denom
    k_edge<8><<<EDGE_BLOCKS, 256>>>(ei);
    k_post<8><<<POST_BLOCKS, 256>>>(b1, bn2_g, bn2_b, bn2_m, bn2_v);

    // ---- conv2 (H=1, C=64) ----
    k_gemm64<<<GEMM_BLOCKS, 128>>>(W2);
    k_att<1, 64><<<ATT_BLOCKS, 256>>>(att_src2, att_dst2);  // also zeroes agg/denom
    k_edge<1><<<EDGE_BLOCKS, 256>>>(ei);
    k_post<1><<<POST_BLOCKS, 256>>>(b2, bn3_g, bn3_b, bn3_m, bn3_v);

    // classifier
    k_cls<<<(N_NODES + 127) / 128, 128>>>(cls_W, cls_b, out);
}

// round 14
// speedup vs baseline: 1.5515x; 1.1711x over previous
#include <cuda_runtime.h>
#include <math.h>

#define N_NODES 50000
#define N_EDGES 800000
#define E_TOT   (N_EDGES + N_NODES)   // with self loops = 850000
#define IN_C    768
#define HID     64
#define OUT_C   8
#define BN_EPS  1e-5f
#define NEG_SLOPE 0.2f

typedef unsigned long long u64;

// ---------------- device scratch (allocation-free) ----------------
__device__ float g_h[N_NODES * HID];        // current node features
__device__ float g_xw[N_NODES * HID];       // h @ W per conv
__device__ float g_asrc[N_NODES * 8];
__device__ float g_adst[N_NODES * 8];
__device__ float g_denom[N_NODES * 8];
__device__ float g_agg[N_NODES * HID];      // unnormalized aggregation

// ---------------- helpers ----------------
__device__ __forceinline__ float lrelu(float x) {
    return x > 0.f ? x : NEG_SLOPE * x;
}
__device__ __forceinline__ float elu1(float x) {
    return x > 0.f ? x : (expf(x) - 1.f);
}
__device__ __forceinline__ u64 pk2(float lo, float hi) {
    u64 r; asm("mov.b64 %0, {%1, %2};" : "=l"(r) : "f"(lo), "f"(hi)); return r;
}
__device__ __forceinline__ void fma2(u64& d, u64 a, u64 b) {
    asm("fma.rn.f32x2 %0, %1, %2, %0;" : "+l"(d) : "l"(a), "l"(b));
}
__device__ __forceinline__ float2 upk(u64 v) {
    float2 r; asm("mov.b64 {%0, %1}, %2;" : "=f"(r.x), "=f"(r.y) : "l"(v)); return r;
}
__device__ __forceinline__ void atomicAddF4(float4* p, float4 v) {
#if __CUDA_ARCH__ >= 900
    atomicAdd(p, v);
#else
    atomicAdd(&p->x, v.x); atomicAdd(&p->y, v.y);
    atomicAdd(&p->z, v.z); atomicAdd(&p->w, v.w);
#endif
}
__device__ __forceinline__ void edge_decode(const int* __restrict__ ei, int e,
                                            int& src, int& dst) {
    if (e < N_EDGES) { src = ei[e]; dst = ei[N_EDGES + e]; }
    else             { src = dst = e - N_EDGES; }
}

// ---------------- K1: h = elu(bn1(x @ proj_W + proj_b)) ----------------
// 64x64 tile, 128 threads, 8x4 register block, FFMA2 inner loop (R10 form —
// plain loads; cp.async/reg-prefetch variants measured slower, closed).
__global__ __launch_bounds__(128) void k_gemm_in(
    const float* __restrict__ x, const float* __restrict__ W,
    const float* __restrict__ pb,
    const float* __restrict__ bg, const float* __restrict__ bb,
    const float* __restrict__ bm, const float* __restrict__ bv)
{
    __shared__ float xs[64][65];
    __shared__ float ws[64][64];
    const int tid = threadIdx.x;
    const int r0 = blockIdx.x * 64;
    const int cg = tid & 15;      // 16 col groups of 4
    const int rg = tid >> 4;      // 8 row groups of 8
    u64 acc01[8], acc23[8];
#pragma unroll
    for (int i = 0; i < 8; i++) { acc01[i] = 0ull; acc23[i] = 0ull; }

    for (int kc = 0; kc < IN_C; kc += 64) {
#pragma unroll
        for (int i = 0; i < 8; i++) {
            int s = tid + i * 128;            // float4 slot
            int row = s >> 4, c4 = (s & 15) * 4;
            float4 val = make_float4(0.f, 0.f, 0.f, 0.f);
            int gr = r0 + row;
            if (gr < N_NODES)
                val = *(const float4*)&x[(size_t)gr * IN_C + kc + c4];
            xs[row][c4+0] = val.x; xs[row][c4+1] = val.y;
            xs[row][c4+2] = val.z; xs[row][c4+3] = val.w;
        }
#pragma unroll
        for (int i = 0; i < 8; i++) {
            int s = tid + i * 128;
            int row = s >> 4, c4 = (s & 15) * 4;
            *(float4*)&ws[row][c4] = *(const float4*)&W[(size_t)(kc + row) * HID + c4];
        }
        __syncthreads();
#pragma unroll 8
        for (int k = 0; k < 64; k++) {
            float4 w = *(float4*)&ws[k][cg * 4];
            u64 w01 = pk2(w.x, w.y);
            u64 w23 = pk2(w.z, w.w);
#pragma unroll
            for (int i = 0; i < 8; i++) {
                float xv = xs[rg * 8 + i][k];
                u64 xx = pk2(xv, xv);
                fma2(acc01[i], xx, w01);
                fma2(acc23[i], xx, w23);
            }
        }
        __syncthreads();
    }
    const int c0 = cg * 4;
    float sc[4], of[4];
#pragma unroll
    for (int j = 0; j < 4; j++) {
        int c = c0 + j;
        float s = bg[c] * rsqrtf(bv[c] + BN_EPS);
        sc[j] = s;
        of[j] = (pb[c] - bm[c]) * s + bb[c];
    }
#pragma unroll
    for (int i = 0; i < 8; i++) {
        int gr = r0 + rg * 8 + i;
        if (gr < N_NODES) {
            float2 a01 = upk(acc01[i]);
            float2 a23 = upk(acc23[i]);
            float4 o;
            o.x = elu1(a01.x * sc[0] + of[0]);
            o.y = elu1(a01.y * sc[1] + of[1]);
            o.z = elu1(a23.x * sc[2] + of[2]);
            o.w = elu1(a23.y * sc[3] + of[3]);
            *(float4*)&g_h[(size_t)gr * HID + c0] = o;
        }
    }
}

// ---------------- K2: xw = g_h @ W1 (64x64), conv1 ----------------
__global__ __launch_bounds__(128) void k_gemm64(const float* __restrict__ W)
{
    __shared__ float xs[64][65];
    __shared__ float ws[64][64];
    const int tid = threadIdx.x;
    const int r0 = blockIdx.x * 64;
    const int cg = tid & 15;
    const int rg = tid >> 4;
    u64 acc01[8], acc23[8];
#pragma unroll
    for (int i = 0; i < 8; i++) { acc01[i] = 0ull; acc23[i] = 0ull; }

#pragma unroll
    for (int i = 0; i < 8; i++) {
        int s = tid + i * 128;
        int row = s >> 4, c4 = (s & 15) * 4;
        float4 val = make_float4(0.f, 0.f, 0.f, 0.f);
        int gr = r0 + row;
        if (gr < N_NODES)
            val = *(const float4*)&g_h[(size_t)gr * HID + c4];
        xs[row][c4+0] = val.x; xs[row][c4+1] = val.y;
        xs[row][c4+2] = val.z; xs[row][c4+3] = val.w;
        *(float4*)&ws[row][c4] = *(const float4*)&W[(size_t)row * HID + c4];
    }
    __syncthreads();
#pragma unroll 8
    for (int k = 0; k < 64; k++) {
        float4 w = *(float4*)&ws[k][cg * 4];
        u64 w01 = pk2(w.x, w.y);
        u64 w23 = pk2(w.z, w.w);
#pragma unroll
        for (int i = 0; i < 8; i++) {
            float xv = xs[rg * 8 + i][k];
            u64 xx = pk2(xv, xv);
            fma2(acc01[i], xx, w01);
            fma2(acc23[i], xx, w23);
        }
    }
    const int c0 = cg * 4;
#pragma unroll
    for (int i = 0; i < 8; i++) {
        int gr = r0 + rg * 8 + i;
        if (gr < N_NODES) {
            float2 a01 = upk(acc01[i]);
            float2 a23 = upk(acc23[i]);
            *(float4*)&g_xw[(size_t)gr * HID + c0] =
                make_float4(a01.x, a01.y, a23.x, a23.y);
        }
    }
}

// ---- K2b: conv2 GEMM with FUSED conv1-post in the load stage -----------
// h = elu(bn2(agg/denom + b1) + h_old); writes g_h (conv2 identity) and
// computes xw = h @ W2. Replaces k_post<8> + k_gemm64. (Correctness proven
// in the R11 passing run.)
__global__ __launch_bounds__(128) void k_gemm64_post(
    const float* __restrict__ W,
    const float* __restrict__ bias,
    const float* __restrict__ bg, const float* __restrict__ bb,
    const float* __restrict__ bm, const float* __restrict__ bv)
{
    __shared__ float xs[64][65];
    __shared__ float ws[64][64];
    const int tid = threadIdx.x;
    const int r0 = blockIdx.x * 64;
    const int cg = tid & 15;
    const int rg = tid >> 4;
    u64 acc01[8], acc23[8];
#pragma unroll
    for (int i = 0; i < 8; i++) { acc01[i] = 0ull; acc23[i] = 0ull; }

#pragma unroll
    for (int i = 0; i < 8; i++) {
        int s = tid + i * 128;
        int row = s >> 4, c4 = (s & 15) * 4;
        int gr = r0 + row;
        float4 o = make_float4(0.f, 0.f, 0.f, 0.f);
        if (gr < N_NODES) {
            float4 a  = *(const float4*)&g_agg[(size_t)gr * HID + c4];
            float4 ho = *(const float4*)&g_h[(size_t)gr * HID + c4];
            float inv = 1.f / g_denom[gr * 8 + (c4 >> 3)];
            float av[4] = { a.x * inv, a.y * inv, a.z * inv, a.w * inv };
            float hv[4] = { ho.x, ho.y, ho.z, ho.w };
            float ov[4];
#pragma unroll
            for (int jj = 0; jj < 4; jj++) {
                int c = c4 + jj;
                float sfac = bg[c] * rsqrtf(bv[c] + BN_EPS);
                float t = (av[jj] + bias[c] - bm[c]) * sfac + bb[c] + hv[jj];
                ov[jj] = elu1(t);
            }
            o = make_float4(ov[0], ov[1], ov[2], ov[3]);
            *(float4*)&g_h[(size_t)gr * HID + c4] = o;   // conv2 identity
        }
        xs[row][c4+0] = o.x; xs[row][c4+1] = o.y;
        xs[row][c4+2] = o.z; xs[row][c4+3] = o.w;
        *(float4*)&ws[row][c4] = *(const float4*)&W[(size_t)row * HID + c4];
    }
    __syncthreads();
#pragma unroll 8
    for (int k = 0; k < 64; k++) {
        float4 w = *(float4*)&ws[k][cg * 4];
        u64 w01 = pk2(w.x, w.y);
        u64 w23 = pk2(w.z, w.w);
#pragma unroll
        for (int i = 0; i < 8; i++) {
            float xv = xs[rg * 8 + i][k];
            u64 xx = pk2(xv, xv);
            fma2(acc01[i], xx, w01);
            fma2(acc23[i], xx, w23);
        }
    }
    const int c0 = cg * 4;
#pragma unroll
    for (int i = 0; i < 8; i++) {
        int gr = r0 + rg * 8 + i;
        if (gr < N_NODES) {
            float2 a01 = upk(acc01[i]);
            float2 a23 = upk(acc23[i]);
            *(float4*)&g_xw[(size_t)gr * HID + c0] =
                make_float4(a01.x, a01.y, a23.x, a23.y);
        }
    }
}

// ---------------- K3: per-node attention logits + accumulator zeroing ----
template<int H, int C>
__global__ void k_att(const float* __restrict__ att_s,
                      const float* __restrict__ att_d)
{
    int warp = (blockIdx.x * blockDim.x + threadIdx.x) >> 5;
    int lane = threadIdx.x & 31;
    if (warp >= N_NODES) return;

    // zero accumulators for this node (consumed by k_edge next)
    *(float2*)&g_agg[(size_t)warp * HID + lane * 2] = make_float2(0.f, 0.f);
    if (H == 8) {
        if (lane < 8) g_denom[warp * 8 + lane] = 0.f;
    } else {
        if (lane == 0) g_denom[warp] = 0.f;
    }

    float2 xv = *(const float2*)&g_xw[warp * HID + lane * 2];
    float2 as = *(const float2*)&att_s[lane * 2];
    float2 ad = *(const float2*)&att_d[lane * 2];
    float ps = xv.x * as.x + xv.y * as.y;
    float pd = xv.x * ad.x + xv.y * ad.y;
    const int G = C / 2;   // lanes per head
#pragma unroll
    for (int off = G >> 1; off > 0; off >>= 1) {
        ps += __shfl_xor_sync(0xffffffffu, ps, off);
        pd += __shfl_xor_sync(0xffffffffu, pd, off);
    }
    if ((lane & (G - 1)) == 0) {
        int h = lane / G;
        g_asrc[warp * H + h] = ps;
        g_adst[warp * H + h] = pd;
    }
}

// ---------------- K5: FUSED edge pass ----------------
// 8 threads per edge; lane j handles head j (H=8) / features j*8..j*8+7.
template<int H>
__global__ void k_edge(const int* __restrict__ ei)
{
    int t = blockIdx.x * blockDim.x + threadIdx.x;
    int j = t & 7;
    int e = t >> 3;
    if (e >= E_TOT) return;
    int src, dst;
    edge_decode(ei, e, src, dst);
    float ex;
    if (H == 8) {
        float a = g_asrc[src * 8 + j] + g_adst[dst * 8 + j];
        ex = expf(lrelu(a));
        atomicAdd(&g_denom[dst * 8 + j], ex);
    } else {
        float a = g_asrc[src] + g_adst[dst];
        ex = expf(lrelu(a));
        if (j == 0) atomicAdd(&g_denom[dst], ex);
    }
    const float4* xp = (const float4*)&g_xw[src * HID + j * 8];
    float4 a = xp[0], b = xp[1];
    a.x *= ex; a.y *= ex; a.z *= ex; a.w *= ex;
    b.x *= ex; b.y *= ex; b.z *= ex; b.w *= ex;
    atomicAddF4((float4*)&g_agg[dst * HID + j * 8], a);
    atomicAddF4((float4*)&g_agg[dst * HID + j * 8 + 4], b);
}

// ---------------- K7: classifier with FUSED conv2-post -------------------
// h_final = elu(bn3(agg/denom + b2) + h_old) computed in the load stage,
// then out = h_final @ cls_W + cls_b. Replaces k_post<1> + k_cls.
__global__ __launch_bounds__(128) void k_cls_post(
    const float* __restrict__ W, const float* __restrict__ biasc,
    const float* __restrict__ bias2,
    const float* __restrict__ bg, const float* __restrict__ bb,
    const float* __restrict__ bm, const float* __restrict__ bv,
    float* __restrict__ out)
{
    __shared__ float hs[128][65];
    __shared__ float ws[64][8];
    const int tid = threadIdx.x;
    const int n0 = blockIdx.x * 128;
#pragma unroll
    for (int i = 0; i < 4; i++) {
        int s = tid + i * 128;
        ws[s >> 3][s & 7] = W[s];
    }
#pragma unroll
    for (int i = 0; i < 16; i++) {
        int s = tid + i * 128;            // float4 slot
        int row = s >> 4, c4 = (s & 15) * 4;
        int node = n0 + row;
        float4 o = make_float4(0.f, 0.f, 0.f, 0.f);
        if (node < N_NODES) {
            float4 a  = *(const float4*)&g_agg[(size_t)node * HID + c4];
            float4 ho = *(const float4*)&g_h[(size_t)node * HID + c4];
            float inv = 1.f / g_denom[node];          // H=1
            float av[4] = { a.x * inv, a.y * inv, a.z * inv, a.w * inv };
            float hv[4] = { ho.x, ho.y, ho.z, ho.w };
            float ov[4];
#pragma unroll
            for (int jj = 0; jj < 4; jj++) {
                int c = c4 + jj;
                float sfac = bg[c] * rsqrtf(bv[c] + BN_EPS);
                float t = (av[jj] + bias2[c] - bm[c]) * sfac + bb[c] + hv[jj];
                ov[jj] = elu1(t);
            }
            o = make_float4(ov[0], ov[1], ov[2], ov[3]);
        }
        hs[row][c4+0] = o.x; hs[row][c4+1] = o.y;
        hs[row][c4+2] = o.z; hs[row][c4+3] = o.w;
    }
    __syncthreads();
    if (n0 + tid >= N_NODES) return;
    float acc[8];
#pragma unroll
    for (int jj = 0; jj < 8; jj++) acc[jj] = biasc[jj];
#pragma unroll 8
    for (int k = 0; k < 64; k++) {
        float xv = hs[tid][k];
        float4 w0 = *(float4*)&ws[k][0];
        float4 w1 = *(float4*)&ws[k][4];
        acc[0] += xv * w0.x; acc[1] += xv * w0.y;
        acc[2] += xv * w0.z; acc[3] += xv * w0.w;
        acc[4] += xv * w1.x; acc[5] += xv * w1.y;
        acc[6] += xv * w1.z; acc[7] += xv * w1.w;
    }
    float* op = &out[(size_t)(n0 + tid) * 8];
    *(float4*)&op[0] = make_float4(acc[0], acc[1], acc[2], acc[3]);
    *(float4*)&op[4] = make_float4(acc[4], acc[5], acc[6], acc[7]);
}

// ---------------- launch ----------------
extern "C" void kernel_launch(void* const* d_in, const int* in_sizes, int n_in,
                              void* d_out, int out_size)
{
    const float* x        = (const float*)d_in[0];
    const int*   ei       = (const int*)  d_in[1];
    const float* proj_W   = (const float*)d_in[2];
    const float* proj_b   = (const float*)d_in[3];
    const float* bn1_g    = (const float*)d_in[4];
    const float* bn1_b    = (const float*)d_in[5];
    const float* bn1_m    = (const float*)d_in[6];
    const float* bn1_v    = (const float*)d_in[7];
    const float* bn2_g    = (const float*)d_in[8];
    const float* bn2_b    = (const float*)d_in[9];
    const float* bn2_m    = (const float*)d_in[10];
    const float* bn2_v    = (const float*)d_in[11];
    const float* bn3_g    = (const float*)d_in[12];
    const float* bn3_b    = (const float*)d_in[13];
    const float* bn3_m    = (const float*)d_in[14];
    const float* bn3_v    = (const float*)d_in[15];
    const float* W1       = (const float*)d_in[16];
    const float* att_src1 = (const float*)d_in[17];
    const float* att_dst1 = (const float*)d_in[18];
    const float* b1       = (const float*)d_in[19];
    const float* W2       = (const float*)d_in[20];
    const float* att_src2 = (const float*)d_in[21];
    const float* att_dst2 = (const float*)d_in[22];
    const float* b2       = (const float*)d_in[23];
    const float* cls_W    = (const float*)d_in[24];
    const float* cls_b    = (const float*)d_in[25];
    float* out = (float*)d_out;

    const int GEMM_BLOCKS = (N_NODES + 63) / 64;              // 782
    const int EDGE_BLOCKS = (E_TOT * 8 + 255) / 256;          // 26563
    const int ATT_BLOCKS  = (N_NODES + 7) / 8;                // 6250

    // projection + bn1 + elu
    k_gemm_in<<<GEMM_BLOCKS, 128>>>(x, proj_W, proj_b, bn1_g, bn1_b, bn1_m, bn1_v);

    // ---- conv1 (H=8, C=8) ----
    k_gemm64<<<GEMM_BLOCKS, 128>>>(W1);
    k_att<8, 8><<<ATT_BLOCKS, 256>>>(att_src1, att_dst1);   // also zeroes agg/denom
    k_edge<8><<<EDGE_BLOCKS, 256>>>(ei);

    // ---- conv2 (H=1, C=64); conv1-post fused into its GEMM ----
    k_gemm64_post<<<GEMM_BLOCKS, 128>>>(W2, b1, bn2_g, bn2_b, bn2_m, bn2_v);
    k_att<1, 64><<<ATT_BLOCKS, 256>>>(att_src2, att_dst2);  // also zeroes agg/denom
    k_edge<1><<<EDGE_BLOCKS, 256>>>(ei);

    // classifier; conv2-post fused into its load stage
    k_cls_post<<<(N_NODES + 127) / 128, 128>>>(cls_W, cls_b, b2,
                                               bn3_g, bn3_b, bn3_m, bn3_v, out);
}

// round 15
// speedup vs baseline: 1.6763x; 1.0805x over previous
#include <cuda_runtime.h>
#include <math.h>

#define N_NODES 50000
#define N_EDGES 800000
#define E_TOT   (N_EDGES + N_NODES)   // with self loops = 850000
#define IN_C    768
#define HID     64
#define OUT_C   8
#define BN_EPS  1e-5f
#define NEG_SLOPE 0.2f

typedef unsigned long long u64;

// ---------------- device scratch (allocation-free) ----------------
__device__ float g_h[N_NODES * HID];        // current node features
__device__ float g_xw[N_NODES * HID];       // h @ W per conv
__device__ float g_asrc[N_NODES * 8];
__device__ float g_adst[N_NODES * 8];
__device__ float g_denom[N_NODES * 8];
__device__ float g_agg[N_NODES * HID];      // unnormalized aggregation

// ---------------- helpers ----------------
__device__ __forceinline__ float lrelu(float x) {
    return x > 0.f ? x : NEG_SLOPE * x;
}
__device__ __forceinline__ float elu1(float x) {
    return x > 0.f ? x : (expf(x) - 1.f);
}
__device__ __forceinline__ u64 pk2(float lo, float hi) {
    u64 r; asm("mov.b64 %0, {%1, %2};" : "=l"(r) : "f"(lo), "f"(hi)); return r;
}
__device__ __forceinline__ void fma2(u64& d, u64 a, u64 b) {
    asm("fma.rn.f32x2 %0, %1, %2, %0;" : "+l"(d) : "l"(a), "l"(b));
}
__device__ __forceinline__ float2 upk(u64 v) {
    float2 r; asm("mov.b64 {%0, %1}, %2;" : "=f"(r.x), "=f"(r.y) : "l"(v)); return r;
}
__device__ __forceinline__ void atomicAddF4(float4* p, float4 v) {
#if __CUDA_ARCH__ >= 900
    atomicAdd(p, v);
#else
    atomicAdd(&p->x, v.x); atomicAdd(&p->y, v.y);
    atomicAdd(&p->z, v.z); atomicAdd(&p->w, v.w);
#endif
}
__device__ __forceinline__ void edge_decode(const int* __restrict__ ei, int e,
                                            int& src, int& dst) {
    if (e < N_EDGES) { src = ei[e]; dst = ei[N_EDGES + e]; }
    else             { src = dst = e - N_EDGES; }
}
// tf32 helpers
__device__ __forceinline__ unsigned cvt_tf32(float f) {
    unsigned r; asm("cvt.rna.tf32.f32 %0, %1;" : "=r"(r) : "f"(f)); return r;
}
__device__ __forceinline__ void mma_tf32(float* d, const unsigned* a,
                                         unsigned b0, unsigned b1) {
    asm volatile(
        "mma.sync.aligned.m16n8k8.row.col.f32.tf32.tf32.f32 "
        "{%0,%1,%2,%3}, {%4,%5,%6,%7}, {%8,%9}, {%0,%1,%2,%3};"
        : "+f"(d[0]), "+f"(d[1]), "+f"(d[2]), "+f"(d[3])
        : "r"(a[0]), "r"(a[1]), "r"(a[2]), "r"(a[3]), "r"(b0), "r"(b1));
}

// ---------------- K1: h = elu(bn1(x @ proj_W + proj_b)) ----------------
// Tensor-core tf32 with 3xTF32 compensation (~fp32 accuracy).
// Block: 128 thr (4 warps), tile 64 rows x 64 cols; warp = 16 rows x 64 cols.
// K in chunks of 32 (4 mma k-steps); W-chunk pre-split hi/lo in smem.
__global__ __launch_bounds__(128) void k_gemm_in(
    const float* __restrict__ x, const float* __restrict__ W,
    const float* __restrict__ pb,
    const float* __restrict__ bg, const float* __restrict__ bb,
    const float* __restrict__ bm, const float* __restrict__ bv)
{
    __shared__ float xs[64][36];      // 64 rows x 32 k (pad 36: A-frags conflict-free)
    __shared__ float wh[32][72];      // W-chunk hi (tf32 values; pad 72: B-frags c-free)
    __shared__ float wl[32][72];      // W-chunk lo
    __shared__ float sc_s[64], of_s[64];

    const int tid  = threadIdx.x;
    const int r0   = blockIdx.x * 64;
    const int warp = tid >> 5;
    const int lane = tid & 31;
    const int gid  = lane >> 2;       // 0..7
    const int tig  = lane & 3;        // 0..3
    const int wrow = warp * 16;

    if (tid < 64) {
        float s = bg[tid] * rsqrtf(bv[tid] + BN_EPS);
        sc_s[tid] = s;
        of_s[tid] = (pb[tid] - bm[tid]) * s + bb[tid];
    }

    float acc[8][4];
#pragma unroll
    for (int nt = 0; nt < 8; nt++)
#pragma unroll
        for (int j = 0; j < 4; j++) acc[nt][j] = 0.f;

    for (int kc = 0; kc < IN_C; kc += 32) {
        __syncthreads();   // retire previous chunk's smem readers
        // load x chunk: 64 rows x 32 cols = 512 float4 slots
#pragma unroll
        for (int i = 0; i < 4; i++) {
            int s = tid + i * 128;
            int row = s >> 3, c4 = (s & 7) * 4;
            int gr = r0 + row;
            float4 v = make_float4(0.f, 0.f, 0.f, 0.f);
            if (gr < N_NODES)
                v = *(const float4*)&x[(size_t)gr * IN_C + kc + c4];
            xs[row][c4+0] = v.x; xs[row][c4+1] = v.y;
            xs[row][c4+2] = v.z; xs[row][c4+3] = v.w;
        }
        // load W chunk (32 x 64) and split into tf32 hi/lo
#pragma unroll
        for (int i = 0; i < 4; i++) {
            int s = tid + i * 128;
            int row = s >> 4, c4 = (s & 15) * 4;
            float4 v = *(const float4*)&W[(size_t)(kc + row) * HID + c4];
            float4 h, l;
            h.x = __uint_as_float(cvt_tf32(v.x)); l.x = __uint_as_float(cvt_tf32(v.x - h.x));
            h.y = __uint_as_float(cvt_tf32(v.y)); l.y = __uint_as_float(cvt_tf32(v.y - h.y));
            h.z = __uint_as_float(cvt_tf32(v.z)); l.z = __uint_as_float(cvt_tf32(v.z - h.z));
            h.w = __uint_as_float(cvt_tf32(v.w)); l.w = __uint_as_float(cvt_tf32(v.w - h.w));
            *(float4*)&wh[row][c4] = h;
            *(float4*)&wl[row][c4] = l;
        }
        __syncthreads();
#pragma unroll
        for (int k8 = 0; k8 < 4; k8++) {
            const int klo = k8 * 8;
            // A fragments (m16n8k8 row-major): rows gid/gid+8, cols tig/tig+4
            float af[4];
            af[0] = xs[wrow + gid    ][klo + tig];
            af[1] = xs[wrow + gid + 8][klo + tig];
            af[2] = xs[wrow + gid    ][klo + tig + 4];
            af[3] = xs[wrow + gid + 8][klo + tig + 4];
            unsigned ah[4], al[4];
#pragma unroll
            for (int j = 0; j < 4; j++) {
                ah[j] = cvt_tf32(af[j]);
                al[j] = cvt_tf32(af[j] - __uint_as_float(ah[j]));
            }
#pragma unroll
            for (int nt = 0; nt < 8; nt++) {
                // B fragments (col-major view of W[k][n]): k rows tig/tig+4, col gid
                unsigned bh0 = __float_as_uint(wh[klo + tig    ][nt * 8 + gid]);
                unsigned bh1 = __float_as_uint(wh[klo + tig + 4][nt * 8 + gid]);
                unsigned bl0 = __float_as_uint(wl[klo + tig    ][nt * 8 + gid]);
                unsigned bl1 = __float_as_uint(wl[klo + tig + 4][nt * 8 + gid]);
                mma_tf32(acc[nt], al, bh0, bh1);   // x_lo @ W_hi
                mma_tf32(acc[nt], ah, bl0, bl1);   // x_hi @ W_lo
                mma_tf32(acc[nt], ah, bh0, bh1);   // x_hi @ W_hi
            }
        }
    }
    // epilogue: bn1 + elu.  D layout: c0,c1 at (gid, tig*2(+1)); c2,c3 at (gid+8, ..)
    const int rtop = r0 + wrow + gid;
    const int rbot = rtop + 8;
#pragma unroll
    for (int nt = 0; nt < 8; nt++) {
        int c0 = nt * 8 + tig * 2;
        float s0 = sc_s[c0], s1 = sc_s[c0 + 1];
        float o0 = of_s[c0], o1 = of_s[c0 + 1];
        if (rtop < N_NODES) {
            float2 v = make_float2(elu1(acc[nt][0] * s0 + o0),
                                   elu1(acc[nt][1] * s1 + o1));
            *(float2*)&g_h[(size_t)rtop * HID + c0] = v;
        }
        if (rbot < N_NODES) {
            float2 v = make_float2(elu1(acc[nt][2] * s0 + o0),
                                   elu1(acc[nt][3] * s1 + o1));
            *(float2*)&g_h[(size_t)rbot * HID + c0] = v;
        }
    }
}

// ---------------- K2: xw = g_h @ W1 (64x64), conv1 ----------------
__global__ __launch_bounds__(128) void k_gemm64(const float* __restrict__ W)
{
    __shared__ float xs[64][65];
    __shared__ float ws[64][64];
    const int tid = threadIdx.x;
    const int r0 = blockIdx.x * 64;
    const int cg = tid & 15;
    const int rg = tid >> 4;
    u64 acc01[8], acc23[8];
#pragma unroll
    for (int i = 0; i < 8; i++) { acc01[i] = 0ull; acc23[i] = 0ull; }

#pragma unroll
    for (int i = 0; i < 8; i++) {
        int s = tid + i * 128;
        int row = s >> 4, c4 = (s & 15) * 4;
        float4 val = make_float4(0.f, 0.f, 0.f, 0.f);
        int gr = r0 + row;
        if (gr < N_NODES)
            val = *(const float4*)&g_h[(size_t)gr * HID + c4];
        xs[row][c4+0] = val.x; xs[row][c4+1] = val.y;
        xs[row][c4+2] = val.z; xs[row][c4+3] = val.w;
        *(float4*)&ws[row][c4] = *(const float4*)&W[(size_t)row * HID + c4];
    }
    __syncthreads();
#pragma unroll 8
    for (int k = 0; k < 64; k++) {
        float4 w = *(float4*)&ws[k][cg * 4];
        u64 w01 = pk2(w.x, w.y);
        u64 w23 = pk2(w.z, w.w);
#pragma unroll
        for (int i = 0; i < 8; i++) {
            float xv = xs[rg * 8 + i][k];
            u64 xx = pk2(xv, xv);
            fma2(acc01[i], xx, w01);
            fma2(acc23[i], xx, w23);
        }
    }
    const int c0 = cg * 4;
#pragma unroll
    for (int i = 0; i < 8; i++) {
        int gr = r0 + rg * 8 + i;
        if (gr < N_NODES) {
            float2 a01 = upk(acc01[i]);
            float2 a23 = upk(acc23[i]);
            *(float4*)&g_xw[(size_t)gr * HID + c0] =
                make_float4(a01.x, a01.y, a23.x, a23.y);
        }
    }
}

// ---- K2b: conv2 GEMM with FUSED conv1-post in the load stage -----------
__global__ __launch_bounds__(128) void k_gemm64_post(
    const float* __restrict__ W,
    const float* __restrict__ bias,
    const float* __restrict__ bg, const float* __restrict__ bb,
    const float* __restrict__ bm, const float* __restrict__ bv)
{
    __shared__ float xs[64][65];
    __shared__ float ws[64][64];
    const int tid = threadIdx.x;
    const int r0 = blockIdx.x * 64;
    const int cg = tid & 15;
    const int rg = tid >> 4;
    u64 acc01[8], acc23[8];
#pragma unroll
    for (int i = 0; i < 8; i++) { acc01[i] = 0ull; acc23[i] = 0ull; }

#pragma unroll
    for (int i = 0; i < 8; i++) {
        int s = tid + i * 128;
        int row = s >> 4, c4 = (s & 15) * 4;
        int gr = r0 + row;
        float4 o = make_float4(0.f, 0.f, 0.f, 0.f);
        if (gr < N_NODES) {
            float4 a  = *(const float4*)&g_agg[(size_t)gr * HID + c4];
            float4 ho = *(const float4*)&g_h[(size_t)gr * HID + c4];
            float inv = 1.f / g_denom[gr * 8 + (c4 >> 3)];
            float av[4] = { a.x * inv, a.y * inv, a.z * inv, a.w * inv };
            float hv[4] = { ho.x, ho.y, ho.z, ho.w };
            float ov[4];
#pragma unroll
            for (int jj = 0; jj < 4; jj++) {
                int c = c4 + jj;
                float sfac = bg[c] * rsqrtf(bv[c] + BN_EPS);
                float t = (av[jj] + bias[c] - bm[c]) * sfac + bb[c] + hv[jj];
                ov[jj] = elu1(t);
            }
            o = make_float4(ov[0], ov[1], ov[2], ov[3]);
            *(float4*)&g_h[(size_t)gr * HID + c4] = o;   // conv2 identity
        }
        xs[row][c4+0] = o.x; xs[row][c4+1] = o.y;
        xs[row][c4+2] = o.z; xs[row][c4+3] = o.w;
        *(float4*)&ws[row][c4] = *(const float4*)&W[(size_t)row * HID + c4];
    }
    __syncthreads();
#pragma unroll 8
    for (int k = 0; k < 64; k++) {
        float4 w = *(float4*)&ws[k][cg * 4];
        u64 w01 = pk2(w.x, w.y);
        u64 w23 = pk2(w.z, w.w);
#pragma unroll
        for (int i = 0; i < 8; i++) {
            float xv = xs[rg * 8 + i][k];
            u64 xx = pk2(xv, xv);
            fma2(acc01[i], xx, w01);
            fma2(acc23[i], xx, w23);
        }
    }
    const int c0 = cg * 4;
#pragma unroll
    for (int i = 0; i < 8; i++) {
        int gr = r0 + rg * 8 + i;
        if (gr < N_NODES) {
            float2 a01 = upk(acc01[i]);
            float2 a23 = upk(acc23[i]);
            *(float4*)&g_xw[(size_t)gr * HID + c0] =
                make_float4(a01.x, a01.y, a23.x, a23.y);
        }
    }
}

// ---------------- K3: per-node attention logits + accumulator zeroing ----
template<int H, int C>
__global__ void k_att(const float* __restrict__ att_s,
                      const float* __restrict__ att_d)
{
    int warp = (blockIdx.x * blockDim.x + threadIdx.x) >> 5;
    int lane = threadIdx.x & 31;
    if (warp >= N_NODES) return;

    // zero accumulators for this node (consumed by k_edge next)
    *(float2*)&g_agg[(size_t)warp * HID + lane * 2] = make_float2(0.f, 0.f);
    if (H == 8) {
        if (lane < 8) g_denom[warp * 8 + lane] = 0.f;
    } else {
        if (lane == 0) g_denom[warp] = 0.f;
    }

    float2 xv = *(const float2*)&g_xw[warp * HID + lane * 2];
    float2 as = *(const float2*)&att_s[lane * 2];
    float2 ad = *(const float2*)&att_d[lane * 2];
    float ps = xv.x * as.x + xv.y * as.y;
    float pd = xv.x * ad.x + xv.y * ad.y;
    const int G = C / 2;   // lanes per head
#pragma unroll
    for (int off = G >> 1; off > 0; off >>= 1) {
        ps += __shfl_xor_sync(0xffffffffu, ps, off);
        pd += __shfl_xor_sync(0xffffffffu, pd, off);
    }
    if ((lane & (G - 1)) == 0) {
        int h = lane / G;
        g_asrc[warp * H + h] = ps;
        g_adst[warp * H + h] = pd;
    }
}

// ---------------- K5: FUSED edge pass ----------------
// 8 threads per edge; lane j handles head j (H=8) / features j*8..j*8+7.
template<int H>
__global__ void k_edge(const int* __restrict__ ei)
{
    int t = blockIdx.x * blockDim.x + threadIdx.x;
    int j = t & 7;
    int e = t >> 3;
    if (e >= E_TOT) return;
    int src, dst;
    edge_decode(ei, e, src, dst);
    float ex;
    if (H == 8) {
        float a = g_asrc[src * 8 + j] + g_adst[dst * 8 + j];
        ex = expf(lrelu(a));
        atomicAdd(&g_denom[dst * 8 + j], ex);
    } else {
        float a = g_asrc[src] + g_adst[dst];
        ex = expf(lrelu(a));
        if (j == 0) atomicAdd(&g_denom[dst], ex);
    }
    const float4* xp = (const float4*)&g_xw[src * HID + j * 8];
    float4 a = xp[0], b = xp[1];
    a.x *= ex; a.y *= ex; a.z *= ex; a.w *= ex;
    b.x *= ex; b.y *= ex; b.z *= ex; b.w *= ex;
    atomicAddF4((float4*)&g_agg[dst * HID + j * 8], a);
    atomicAddF4((float4*)&g_agg[dst * HID + j * 8 + 4], b);
}

// ---------------- K7: classifier with FUSED conv2-post -------------------
__global__ __launch_bounds__(128) void k_cls_post(
    const float* __restrict__ W, const float* __restrict__ biasc,
    const float* __restrict__ bias2,
    const float* __restrict__ bg, const float* __restrict__ bb,
    const float* __restrict__ bm, const float* __restrict__ bv,
    float* __restrict__ out)
{
    __shared__ float hs[128][65];
    __shared__ float ws[64][8];
    const int tid = threadIdx.x;
    const int n0 = blockIdx.x * 128;
#pragma unroll
    for (int i = 0; i < 4; i++) {
        int s = tid + i * 128;
        ws[s >> 3][s & 7] = W[s];
    }
#pragma unroll
    for (int i = 0; i < 16; i++) {
        int s = tid + i * 128;            // float4 slot
        int row = s >> 4, c4 = (s & 15) * 4;
        int node = n0 + row;
        float4 o = make_float4(0.f, 0.f, 0.f, 0.f);
        if (node < N_NODES) {
            float4 a  = *(const float4*)&g_agg[(size_t)node * HID + c4];
            float4 ho = *(const float4*)&g_h[(size_t)node * HID + c4];
            float inv = 1.f / g_denom[node];          // H=1
            float av[4] = { a.x * inv, a.y * inv, a.z * inv, a.w * inv };
            float hv[4] = { ho.x, ho.y, ho.z, ho.w };
            float ov[4];
#pragma unroll
            for (int jj = 0; jj < 4; jj++) {
                int c = c4 + jj;
                float sfac = bg[c] * rsqrtf(bv[c] + BN_EPS);
                float t = (av[jj] + bias2[c] - bm[c]) * sfac + bb[c] + hv[jj];
                ov[jj] = elu1(t);
            }
            o = make_float4(ov[0], ov[1], ov[2], ov[3]);
        }
        hs[row][c4+0] = o.x; hs[row][c4+1] = o.y;
        hs[row][c4+2] = o.z; hs[row][c4+3] = o.w;
    }
    __syncthreads();
    if (n0 + tid >= N_NODES) return;
    float acc[8];
#pragma unroll
    for (int jj = 0; jj < 8; jj++) acc[jj] = biasc[jj];
#pragma unroll 8
    for (int k = 0; k < 64; k++) {
        float xv = hs[tid][k];
        float4 w0 = *(float4*)&ws[k][0];
        float4 w1 = *(float4*)&ws[k][4];
        acc[0] += xv * w0.x; acc[1] += xv * w0.y;
        acc[2] += xv * w0.z; acc[3] += xv * w0.w;
        acc[4] += xv * w1.x; acc[5] += xv * w1.y;
        acc[6] += xv * w1.z; acc[7] += xv * w1.w;
    }
    float* op = &out[(size_t)(n0 + tid) * 8];
    *(float4*)&op[0] = make_float4(acc[0], acc[1], acc[2], acc[3]);
    *(float4*)&op[4] = make_float4(acc[4], acc[5], acc[6], acc[7]);
}

// ---------------- launch ----------------
extern "C" void kernel_launch(void* const* d_in, const int* in_sizes, int n_in,
                              void* d_out, int out_size)
{
    const float* x        = (const float*)d_in[0];
    const int*   ei       = (const int*)  d_in[1];
    const float* proj_W   = (const float*)d_in[2];
    const float* proj_b   = (const float*)d_in[3];
    const float* bn1_g    = (const float*)d_in[4];
    const float* bn1_b    = (const float*)d_in[5];
    const float* bn1_m    = (const float*)d_in[6];
    const float* bn1_v    = (const float*)d_in[7];
    const float* bn2_g    = (const float*)d_in[8];
    const float* bn2_b    = (const float*)d_in[9];
    const float* bn2_m    = (const float*)d_in[10];
    const float* bn2_v    = (const float*)d_in[11];
    const float* bn3_g    = (const float*)d_in[12];
    const float* bn3_b    = (const float*)d_in[13];
    const float* bn3_m    = (const float*)d_in[14];
    const float* bn3_v    = (const float*)d_in[15];
    const float* W1       = (const float*)d_in[16];
    const float* att_src1 = (const float*)d_in[17];
    const float* att_dst1 = (const float*)d_in[18];
    const float* b1       = (const float*)d_in[19];
    const float* W2       = (const float*)d_in[20];
    const float* att_src2 = (const float*)d_in[21];
    const float* att_dst2 = (const float*)d_in[22];
    const float* b2       = (const float*)d_in[23];
    const float* cls_W    = (const float*)d_in[24];
    const float* cls_b    = (const float*)d_in[25];
    float* out = (float*)d_out;

    const int GEMM_BLOCKS = (N_NODES + 63) / 64;              // 782
    const int EDGE_BLOCKS = (E_TOT * 8 + 255) / 256;          // 26563
    const int ATT_BLOCKS  = (N_NODES + 7) / 8;                // 6250

    // projection + bn1 + elu (tf32 tensor cores, 3xTF32 compensated)
    k_gemm_in<<<GEMM_BLOCKS, 128>>>(x, proj_W, proj_b, bn1_g, bn1_b, bn1_m, bn1_v);

    // ---- conv1 (H=8, C=8) ----
    k_gemm64<<<GEMM_BLOCKS, 128>>>(W1);
    k_att<8, 8><<<ATT_BLOCKS, 256>>>(att_src1, att_dst1);   // also zeroes agg/denom
    k_edge<8><<<EDGE_BLOCKS, 256>>>(ei);

    // ---- conv2 (H=1, C=64); conv1-post fused into its GEMM ----
    k_gemm64_post<<<GEMM_BLOCKS, 128>>>(W2, b1, bn2_g, bn2_b, bn2_m, bn2_v);
    k_att<1, 64><<<ATT_BLOCKS, 256>>>(att_src2, att_dst2);  // also zeroes agg/denom
    k_edge<1><<<EDGE_BLOCKS, 256>>>(ei);

    // classifier; conv2-post fused into its load stage
    k_cls_post<<<(N_NODES + 127) / 128, 128>>>(cls_W, cls_b, b2,
                                               bn3_g, bn3_b, bn3_m, bn3_v, out);
}

// round 16
// speedup vs baseline: 1.7915x; 1.0688x over previous
#include <cuda_runtime.h>
#include <math.h>

#define N_NODES 50000
#define N_EDGES 800000
#define E_TOT   (N_EDGES + N_NODES)   // with self loops = 850000
#define IN_C    768
#define HID     64
#define OUT_C   8
#define BN_EPS  1e-5f
#define NEG_SLOPE 0.2f

typedef unsigned long long u64;

// ---------------- device scratch (allocation-free) ----------------
__device__ float g_h[N_NODES * HID];        // current node features
__device__ float g_xw[N_NODES * HID];       // h @ W per conv
__device__ float g_asrc[N_NODES * 8];
__device__ float g_adst[N_NODES * 8];
__device__ float g_denom[N_NODES * 8];
__device__ float g_agg[N_NODES * HID];      // unnormalized aggregation

// ---------------- helpers ----------------
__device__ __forceinline__ float lrelu(float x) {
    return x > 0.f ? x : NEG_SLOPE * x;
}
__device__ __forceinline__ float elu1(float x) {
    return x > 0.f ? x : (expf(x) - 1.f);
}
__device__ __forceinline__ u64 pk2(float lo, float hi) {
    u64 r; asm("mov.b64 %0, {%1, %2};" : "=l"(r) : "f"(lo), "f"(hi)); return r;
}
__device__ __forceinline__ void fma2(u64& d, u64 a, u64 b) {
    asm("fma.rn.f32x2 %0, %1, %2, %0;" : "+l"(d) : "l"(a), "l"(b));
}
__device__ __forceinline__ float2 upk(u64 v) {
    float2 r; asm("mov.b64 {%0, %1}, %2;" : "=f"(r.x), "=f"(r.y) : "l"(v)); return r;
}
__device__ __forceinline__ void atomicAddF4(float4* p, float4 v) {
#if __CUDA_ARCH__ >= 900
    atomicAdd(p, v);
#else
    atomicAdd(&p->x, v.x); atomicAdd(&p->y, v.y);
    atomicAdd(&p->z, v.z); atomicAdd(&p->w, v.w);
#endif
}
__device__ __forceinline__ void edge_decode(const int* __restrict__ ei, int e,
                                            int& src, int& dst) {
    if (e < N_EDGES) { src = ei[e]; dst = ei[N_EDGES + e]; }
    else             { src = dst = e - N_EDGES; }
}
// tf32 helpers
__device__ __forceinline__ unsigned cvt_tf32(float f) {
    unsigned r; asm("cvt.rna.tf32.f32 %0, %1;" : "=r"(r) : "f"(f)); return r;
}
__device__ __forceinline__ void mma_tf32(float* d, const unsigned* a,
                                         unsigned b0, unsigned b1) {
    asm volatile(
        "mma.sync.aligned.m16n8k8.row.col.f32.tf32.tf32.f32 "
        "{%0,%1,%2,%3}, {%4,%5,%6,%7}, {%8,%9}, {%0,%1,%2,%3};"
        : "+f"(d[0]), "+f"(d[1]), "+f"(d[2]), "+f"(d[3])
        : "r"(a[0]), "r"(a[1]), "r"(a[2]), "r"(a[3]), "r"(b0), "r"(b1));
}

// ---------------- K1: h = elu(bn1(x @ proj_W + proj_b)) ----------------
// Tensor-core tf32 with 3xTF32 compensation (~fp32 accuracy).
// Block: 128 thr (4 warps), tile 128 rows x 64 cols; warp = 32 rows
// (two m16 A-tiles sharing the SAME B fragments -> B-LDS per output halved).
__global__ __launch_bounds__(128) void k_gemm_in(
    const float* __restrict__ x, const float* __restrict__ W,
    const float* __restrict__ pb,
    const float* __restrict__ bg, const float* __restrict__ bb,
    const float* __restrict__ bm, const float* __restrict__ bv)
{
    __shared__ float xs[128][36];     // 128 rows x 32 k (pad 36: conflict-free)
    __shared__ float wh[32][72];      // W-chunk hi (tf32 values; pad 72)
    __shared__ float wl[32][72];      // W-chunk lo
    __shared__ float sc_s[64], of_s[64];

    const int tid  = threadIdx.x;
    const int r0   = blockIdx.x * 128;
    const int warp = tid >> 5;
    const int lane = tid & 31;
    const int gid  = lane >> 2;       // 0..7
    const int tig  = lane & 3;        // 0..3
    const int wrow = warp * 32;       // warp covers rows wrow..wrow+31

    if (tid < 64) {
        float s = bg[tid] * rsqrtf(bv[tid] + BN_EPS);
        sc_s[tid] = s;
        of_s[tid] = (pb[tid] - bm[tid]) * s + bb[tid];
    }

    float acc[2][8][4];
#pragma unroll
    for (int t = 0; t < 2; t++)
#pragma unroll
        for (int nt = 0; nt < 8; nt++)
#pragma unroll
            for (int j = 0; j < 4; j++) acc[t][nt][j] = 0.f;

    for (int kc = 0; kc < IN_C; kc += 32) {
        __syncthreads();   // retire previous chunk's smem readers
        // load x chunk: 128 rows x 32 cols = 1024 float4 slots
#pragma unroll
        for (int i = 0; i < 8; i++) {
            int s = tid + i * 128;
            int row = s >> 3, c4 = (s & 7) * 4;
            int gr = r0 + row;
            float4 v = make_float4(0.f, 0.f, 0.f, 0.f);
            if (gr < N_NODES)
                v = *(const float4*)&x[(size_t)gr * IN_C + kc + c4];
            xs[row][c4+0] = v.x; xs[row][c4+1] = v.y;
            xs[row][c4+2] = v.z; xs[row][c4+3] = v.w;
        }
        // load W chunk (32 x 64) and split into tf32 hi/lo
#pragma unroll
        for (int i = 0; i < 4; i++) {
            int s = tid + i * 128;
            int row = s >> 4, c4 = (s & 15) * 4;
            float4 v = *(const float4*)&W[(size_t)(kc + row) * HID + c4];
            float4 h, l;
            h.x = __uint_as_float(cvt_tf32(v.x)); l.x = __uint_as_float(cvt_tf32(v.x - h.x));
            h.y = __uint_as_float(cvt_tf32(v.y)); l.y = __uint_as_float(cvt_tf32(v.y - h.y));
            h.z = __uint_as_float(cvt_tf32(v.z)); l.z = __uint_as_float(cvt_tf32(v.z - h.z));
            h.w = __uint_as_float(cvt_tf32(v.w)); l.w = __uint_as_float(cvt_tf32(v.w - h.w));
            *(float4*)&wh[row][c4] = h;
            *(float4*)&wl[row][c4] = l;
        }
        __syncthreads();
#pragma unroll
        for (int k8 = 0; k8 < 4; k8++) {
            const int klo = k8 * 8;
            // A fragments for both 16-row tiles
            unsigned ah[2][4], al[2][4];
#pragma unroll
            for (int t = 0; t < 2; t++) {
                int rb = wrow + t * 16;
                float af[4];
                af[0] = xs[rb + gid    ][klo + tig];
                af[1] = xs[rb + gid + 8][klo + tig];
                af[2] = xs[rb + gid    ][klo + tig + 4];
                af[3] = xs[rb + gid + 8][klo + tig + 4];
#pragma unroll
                for (int j = 0; j < 4; j++) {
                    ah[t][j] = cvt_tf32(af[j]);
                    al[t][j] = cvt_tf32(af[j] - __uint_as_float(ah[t][j]));
                }
            }
#pragma unroll
            for (int nt = 0; nt < 8; nt++) {
                // B fragments shared by both A tiles
                unsigned bh0 = __float_as_uint(wh[klo + tig    ][nt * 8 + gid]);
                unsigned bh1 = __float_as_uint(wh[klo + tig + 4][nt * 8 + gid]);
                unsigned bl0 = __float_as_uint(wl[klo + tig    ][nt * 8 + gid]);
                unsigned bl1 = __float_as_uint(wl[klo + tig + 4][nt * 8 + gid]);
#pragma unroll
                for (int t = 0; t < 2; t++) {
                    mma_tf32(acc[t][nt], al[t], bh0, bh1);   // x_lo @ W_hi
                    mma_tf32(acc[t][nt], ah[t], bl0, bl1);   // x_hi @ W_lo
                    mma_tf32(acc[t][nt], ah[t], bh0, bh1);   // x_hi @ W_hi
                }
            }
        }
    }
    // epilogue: bn1 + elu
#pragma unroll
    for (int t = 0; t < 2; t++) {
        const int rtop = r0 + wrow + t * 16 + gid;
        const int rbot = rtop + 8;
#pragma unroll
        for (int nt = 0; nt < 8; nt++) {
            int c0 = nt * 8 + tig * 2;
            float s0 = sc_s[c0], s1 = sc_s[c0 + 1];
            float o0 = of_s[c0], o1 = of_s[c0 + 1];
            if (rtop < N_NODES) {
                float2 v = make_float2(elu1(acc[t][nt][0] * s0 + o0),
                                       elu1(acc[t][nt][1] * s1 + o1));
                *(float2*)&g_h[(size_t)rtop * HID + c0] = v;
            }
            if (rbot < N_NODES) {
                float2 v = make_float2(elu1(acc[t][nt][2] * s0 + o0),
                                       elu1(acc[t][nt][3] * s1 + o1));
                *(float2*)&g_h[(size_t)rbot * HID + c0] = v;
            }
        }
    }
}

// ---------------- K2: xw = g_h @ W1 (64x64), conv1 ----------------
__global__ __launch_bounds__(128) void k_gemm64(const float* __restrict__ W)
{
    __shared__ float xs[64][65];
    __shared__ float ws[64][64];
    const int tid = threadIdx.x;
    const int r0 = blockIdx.x * 64;
    const int cg = tid & 15;
    const int rg = tid >> 4;
    u64 acc01[8], acc23[8];
#pragma unroll
    for (int i = 0; i < 8; i++) { acc01[i] = 0ull; acc23[i] = 0ull; }

#pragma unroll
    for (int i = 0; i < 8; i++) {
        int s = tid + i * 128;
        int row = s >> 4, c4 = (s & 15) * 4;
        float4 val = make_float4(0.f, 0.f, 0.f, 0.f);
        int gr = r0 + row;
        if (gr < N_NODES)
            val = *(const float4*)&g_h[(size_t)gr * HID + c4];
        xs[row][c4+0] = val.x; xs[row][c4+1] = val.y;
        xs[row][c4+2] = val.z; xs[row][c4+3] = val.w;
        *(float4*)&ws[row][c4] = *(const float4*)&W[(size_t)row * HID + c4];
    }
    __syncthreads();
#pragma unroll 8
    for (int k = 0; k < 64; k++) {
        float4 w = *(float4*)&ws[k][cg * 4];
        u64 w01 = pk2(w.x, w.y);
        u64 w23 = pk2(w.z, w.w);
#pragma unroll
        for (int i = 0; i < 8; i++) {
            float xv = xs[rg * 8 + i][k];
            u64 xx = pk2(xv, xv);
            fma2(acc01[i], xx, w01);
            fma2(acc23[i], xx, w23);
        }
    }
    const int c0 = cg * 4;
#pragma unroll
    for (int i = 0; i < 8; i++) {
        int gr = r0 + rg * 8 + i;
        if (gr < N_NODES) {
            float2 a01 = upk(acc01[i]);
            float2 a23 = upk(acc23[i]);
            *(float4*)&g_xw[(size_t)gr * HID + c0] =
                make_float4(a01.x, a01.y, a23.x, a23.y);
        }
    }
}

// ---- K2b: conv2 GEMM with FUSED conv1-post in the load stage -----------
__global__ __launch_bounds__(128) void k_gemm64_post(
    const float* __restrict__ W,
    const float* __restrict__ bias,
    const float* __restrict__ bg, const float* __restrict__ bb,
    const float* __restrict__ bm, const float* __restrict__ bv)
{
    __shared__ float xs[64][65];
    __shared__ float ws[64][64];
    const int tid = threadIdx.x;
    const int r0 = blockIdx.x * 64;
    const int cg = tid & 15;
    const int rg = tid >> 4;
    u64 acc01[8], acc23[8];
#pragma unroll
    for (int i = 0; i < 8; i++) { acc01[i] = 0ull; acc23[i] = 0ull; }

#pragma unroll
    for (int i = 0; i < 8; i++) {
        int s = tid + i * 128;
        int row = s >> 4, c4 = (s & 15) * 4;
        int gr = r0 + row;
        float4 o = make_float4(0.f, 0.f, 0.f, 0.f);
        if (gr < N_NODES) {
            float4 a  = *(const float4*)&g_agg[(size_t)gr * HID + c4];
            float4 ho = *(const float4*)&g_h[(size_t)gr * HID + c4];
            float inv = 1.f / g_denom[gr * 8 + (c4 >> 3)];
            float av[4] = { a.x * inv, a.y * inv, a.z * inv, a.w * inv };
            float hv[4] = { ho.x, ho.y, ho.z, ho.w };
            float ov[4];
#pragma unroll
            for (int jj = 0; jj < 4; jj++) {
                int c = c4 + jj;
                float sfac = bg[c] * rsqrtf(bv[c] + BN_EPS);
                float t = (av[jj] + bias[c] - bm[c]) * sfac + bb[c] + hv[jj];
                ov[jj] = elu1(t);
            }
            o = make_float4(ov[0], ov[1], ov[2], ov[3]);
            *(float4*)&g_h[(size_t)gr * HID + c4] = o;   // conv2 identity
        }
        xs[row][c4+0] = o.x; xs[row][c4+1] = o.y;
        xs[row][c4+2] = o.z; xs[row][c4+3] = o.w;
        *(float4*)&ws[row][c4] = *(const float4*)&W[(size_t)row * HID + c4];
    }
    __syncthreads();
#pragma unroll 8
    for (int k = 0; k < 64; k++) {
        float4 w = *(float4*)&ws[k][cg * 4];
        u64 w01 = pk2(w.x, w.y);
        u64 w23 = pk2(w.z, w.w);
#pragma unroll
        for (int i = 0; i < 8; i++) {
            float xv = xs[rg * 8 + i][k];
            u64 xx = pk2(xv, xv);
            fma2(acc01[i], xx, w01);
            fma2(acc23[i], xx, w23);
        }
    }
    const int c0 = cg * 4;
#pragma unroll
    for (int i = 0; i < 8; i++) {
        int gr = r0 + rg * 8 + i;
        if (gr < N_NODES) {
            float2 a01 = upk(acc01[i]);
            float2 a23 = upk(acc23[i]);
            *(float4*)&g_xw[(size_t)gr * HID + c0] =
                make_float4(a01.x, a01.y, a23.x, a23.y);
        }
    }
}

// ---------------- K3: per-node attention logits + accumulator zeroing ----
template<int H, int C>
__global__ void k_att(const float* __restrict__ att_s,
                      const float* __restrict__ att_d)
{
    int warp = (blockIdx.x * blockDim.x + threadIdx.x) >> 5;
    int lane = threadIdx.x & 31;
    if (warp >= N_NODES) return;

    // zero accumulators for this node (consumed by k_edge next)
    *(float2*)&g_agg[(size_t)warp * HID + lane * 2] = make_float2(0.f, 0.f);
    if (H == 8) {
        if (lane < 8) g_denom[warp * 8 + lane] = 0.f;
    } else {
        if (lane == 0) g_denom[warp] = 0.f;
    }

    float2 xv = *(const float2*)&g_xw[warp * HID + lane * 2];
    float2 as = *(const float2*)&att_s[lane * 2];
    float2 ad = *(const float2*)&att_d[lane * 2];
    float ps = xv.x * as.x + xv.y * as.y;
    float pd = xv.x * ad.x + xv.y * ad.y;
    const int G = C / 2;   // lanes per head
#pragma unroll
    for (int off = G >> 1; off > 0; off >>= 1) {
        ps += __shfl_xor_sync(0xffffffffu, ps, off);
        pd += __shfl_xor_sync(0xffffffffu, pd, off);
    }
    if ((lane & (G - 1)) == 0) {
        int h = lane / G;
        g_asrc[warp * H + h] = ps;
        g_adst[warp * H + h] = pd;
    }
}

// ---------------- K5: FUSED edge pass ----------------
// 8 threads per edge; lane j handles head j (H=8) / features j*8..j*8+7.
template<int H>
__global__ void k_edge(const int* __restrict__ ei)
{
    int t = blockIdx.x * blockDim.x + threadIdx.x;
    int j = t & 7;
    int e = t >> 3;
    if (e >= E_TOT) return;
    int src, dst;
    edge_decode(ei, e, src, dst);
    float ex;
    if (H == 8) {
        float a = g_asrc[src * 8 + j] + g_adst[dst * 8 + j];
        ex = expf(lrelu(a));
        atomicAdd(&g_denom[dst * 8 + j], ex);
    } else {
        float a = g_asrc[src] + g_adst[dst];
        ex = expf(lrelu(a));
        if (j == 0) atomicAdd(&g_denom[dst], ex);
    }
    const float4* xp = (const float4*)&g_xw[src * HID + j * 8];
    float4 a = xp[0], b = xp[1];
    a.x *= ex; a.y *= ex; a.z *= ex; a.w *= ex;
    b.x *= ex; b.y *= ex; b.z *= ex; b.w *= ex;
    atomicAddF4((float4*)&g_agg[dst * HID + j * 8], a);
    atomicAddF4((float4*)&g_agg[dst * HID + j * 8 + 4], b);
}

// ---------------- K7: classifier with FUSED conv2-post -------------------
__global__ __launch_bounds__(128) void k_cls_post(
    const float* __restrict__ W, const float* __restrict__ biasc,
    const float* __restrict__ bias2,
    const float* __restrict__ bg, const float* __restrict__ bb,
    const float* __restrict__ bm, const float* __restrict__ bv,
    float* __restrict__ out)
{
    __shared__ float hs[128][65];
    __shared__ float ws[64][8];
    const int tid = threadIdx.x;
    const int n0 = blockIdx.x * 128;
#pragma unroll
    for (int i = 0; i < 4; i++) {
        int s = tid + i * 128;
        ws[s >> 3][s & 7] = W[s];
    }
#pragma unroll
    for (int i = 0; i < 16; i++) {
        int s = tid + i * 128;            // float4 slot
        int row = s >> 4, c4 = (s & 15) * 4;
        int node = n0 + row;
        float4 o = make_float4(0.f, 0.f, 0.f, 0.f);
        if (node < N_NODES) {
            float4 a  = *(const float4*)&g_agg[(size_t)node * HID + c4];
            float4 ho = *(const float4*)&g_h[(size_t)node * HID + c4];
            float inv = 1.f / g_denom[node];          // H=1
            float av[4] = { a.x * inv, a.y * inv, a.z * inv, a.w * inv };
            float hv[4] = { ho.x, ho.y, ho.z, ho.w };
            float ov[4];
#pragma unroll
            for (int jj = 0; jj < 4; jj++) {
                int c = c4 + jj;
                float sfac = bg[c] * rsqrtf(bv[c] + BN_EPS);
                float t = (av[jj] + bias2[c] - bm[c]) * sfac + bb[c] + hv[jj];
                ov[jj] = elu1(t);
            }
            o = make_float4(ov[0], ov[1], ov[2], ov[3]);
        }
        hs[row][c4+0] = o.x; hs[row][c4+1] = o.y;
        hs[row][c4+2] = o.z; hs[row][c4+3] = o.w;
    }
    __syncthreads();
    if (n0 + tid >= N_NODES) return;
    float acc[8];
#pragma unroll
    for (int jj = 0; jj < 8; jj++) acc[jj] = biasc[jj];
#pragma unroll 8
    for (int k = 0; k < 64; k++) {
        float xv = hs[tid][k];
        float4 w0 = *(float4*)&ws[k][0];
        float4 w1 = *(float4*)&ws[k][4];
        acc[0] += xv * w0.x; acc[1] += xv * w0.y;
        acc[2] += xv * w0.z; acc[3] += xv * w0.w;
        acc[4] += xv * w1.x; acc[5] += xv * w1.y;
        acc[6] += xv * w1.z; acc[7] += xv * w1.w;
    }
    float* op = &out[(size_t)(n0 + tid) * 8];
    *(float4*)&op[0] = make_float4(acc[0], acc[1], acc[2], acc[3]);
    *(float4*)&op[4] = make_float4(acc[4], acc[5], acc[6], acc[7]);
}

// ---------------- launch ----------------
extern "C" void kernel_launch(void* const* d_in, const int* in_sizes, int n_in,
                              void* d_out, int out_size)
{
    const float* x        = (const float*)d_in[0];
    const int*   ei       = (const int*)  d_in[1];
    const float* proj_W   = (const float*)d_in[2];
    const float* proj_b   = (const float*)d_in[3];
    const float* bn1_g    = (const float*)d_in[4];
    const float* bn1_b    = (const float*)d_in[5];
    const float* bn1_m    = (const float*)d_in[6];
    const float* bn1_v    = (const float*)d_in[7];
    const float* bn2_g    = (const float*)d_in[8];
    const float* bn2_b    = (const float*)d_in[9];
    const float* bn2_m    = (const float*)d_in[10];
    const float* bn2_v    = (const float*)d_in[11];
    const float* bn3_g    = (const float*)d_in[12];
    const float* bn3_b    = (const float*)d_in[13];
    const float* bn3_m    = (const float*)d_in[14];
    const float* bn3_v    = (const float*)d_in[15];
    const float* W1       = (const float*)d_in[16];
    const float* att_src1 = (const float*)d_in[17];
    const float* att_dst1 = (const float*)d_in[18];
    const float* b1       = (const float*)d_in[19];
    const float* W2       = (const float*)d_in[20];
    const float* att_src2 = (const float*)d_in[21];
    const float* att_dst2 = (const float*)d_in[22];
    const float* b2       = (const float*)d_in[23];
    const float* cls_W    = (const float*)d_in[24];
    const float* cls_b    = (const float*)d_in[25];
    float* out = (float*)d_out;

    const int GEMM_IN_BLOCKS = (N_NODES + 127) / 128;         // 391
    const int GEMM_BLOCKS = (N_NODES + 63) / 64;              // 782
    const int EDGE_BLOCKS = (E_TOT * 8 + 255) / 256;          // 26563
    const int ATT_BLOCKS  = (N_NODES + 7) / 8;                // 6250

    // projection + bn1 + elu (tf32 tensor cores, 3xTF32 compensated)
    k_gemm_in<<<GEMM_IN_BLOCKS, 128>>>(x, proj_W, proj_b, bn1_g, bn1_b, bn1_m, bn1_v);

    // ---- conv1 (H=8, C=8) ----
    k_gemm64<<<GEMM_BLOCKS, 128>>>(W1);
    k_att<8, 8><<<ATT_BLOCKS, 256>>>(att_src1, att_dst1);   // also zeroes agg/denom
    k_edge<8><<<EDGE_BLOCKS, 256>>>(ei);

    // ---- conv2 (H=1, C=64); conv1-post fused into its GEMM ----
    k_gemm64_post<<<GEMM_BLOCKS, 128>>>(W2, b1, bn2_g, bn2_b, bn2_m, bn2_v);
    k_att<1, 64><<<ATT_BLOCKS, 256>>>(att_src2, att_dst2);  // also zeroes agg/denom
    k_edge<1><<<EDGE_BLOCKS, 256>>>(ei);

    // classifier; conv2-post fused into its load stage
    k_cls_post<<<(N_NODES + 127) / 128, 128>>>(cls_W, cls_b, b2,
                                               bn3_g, bn3_b, bn3_m, bn3_v, out);
}

// round 17
// speedup vs baseline: 1.8209x; 1.0164x over previous
#include <cuda_runtime.h>
#include <math.h>

#define N_NODES 50000
#define N_EDGES 800000
#define E_TOT   (N_EDGES + N_NODES)   // with self loops = 850000
#define IN_C    768
#define HID     64
#define OUT_C   8
#define BN_EPS  1e-5f
#define NEG_SLOPE 0.2f

typedef unsigned long long u64;

// ---------------- device scratch (allocation-free) ----------------
__device__ float g_h[N_NODES * HID];        // current node features
__device__ float g_xw[N_NODES * HID];       // h @ W per conv
__device__ float g_asrc[N_NODES * 8];
__device__ float g_adst[N_NODES * 8];
__device__ float g_denom[N_NODES * 8];
__device__ float g_agg[N_NODES * HID];      // unnormalized aggregation

// ---------------- helpers ----------------
__device__ __forceinline__ float lrelu(float x) {
    return x > 0.f ? x : NEG_SLOPE * x;
}
__device__ __forceinline__ float elu1(float x) {
    return x > 0.f ? x : (expf(x) - 1.f);
}
__device__ __forceinline__ u64 pk2(float lo, float hi) {
    u64 r; asm("mov.b64 %0, {%1, %2};" : "=l"(r) : "f"(lo), "f"(hi)); return r;
}
__device__ __forceinline__ void fma2(u64& d, u64 a, u64 b) {
    asm("fma.rn.f32x2 %0, %1, %2, %0;" : "+l"(d) : "l"(a), "l"(b));
}
__device__ __forceinline__ float2 upk(u64 v) {
    float2 r; asm("mov.b64 {%0, %1}, %2;" : "=f"(r.x), "=f"(r.y) : "l"(v)); return r;
}
__device__ __forceinline__ void atomicAddF4(float4* p, float4 v) {
#if __CUDA_ARCH__ >= 900
    atomicAdd(p, v);
#else
    atomicAdd(&p->x, v.x); atomicAdd(&p->y, v.y);
    atomicAdd(&p->z, v.z); atomicAdd(&p->w, v.w);
#endif
}
__device__ __forceinline__ void edge_decode(const int* __restrict__ ei, int e,
                                            int& src, int& dst) {
    if (e < N_EDGES) { src = ei[e]; dst = ei[N_EDGES + e]; }
    else             { src = dst = e - N_EDGES; }
}
// tf32 helpers
__device__ __forceinline__ unsigned cvt_tf32(float f) {
    unsigned r; asm("cvt.rna.tf32.f32 %0, %1;" : "=r"(r) : "f"(f)); return r;
}
__device__ __forceinline__ void mma_tf32(float* d, const unsigned* a,
                                         unsigned b0, unsigned b1) {
    asm volatile(
        "mma.sync.aligned.m16n8k8.row.col.f32.tf32.tf32.f32 "
        "{%0,%1,%2,%3}, {%4,%5,%6,%7}, {%8,%9}, {%0,%1,%2,%3};"
        : "+f"(d[0]), "+f"(d[1]), "+f"(d[2]), "+f"(d[3])
        : "r"(a[0]), "r"(a[1]), "r"(a[2]), "r"(a[3]), "r"(b0), "r"(b1));
}

// ---------------- K1: h = elu(bn1(x @ proj_W + proj_b)) ----------------
// Tensor-core tf32 with 3xTF32 compensation (~fp32 accuracy).
// Block: 128 thr (4 warps), tile 128 rows x 64 cols; warp = 32 rows
// (two m16 A-tiles sharing the SAME B fragments).
__global__ __launch_bounds__(128) void k_gemm_in(
    const float* __restrict__ x, const float* __restrict__ W,
    const float* __restrict__ pb,
    const float* __restrict__ bg, const float* __restrict__ bb,
    const float* __restrict__ bm, const float* __restrict__ bv)
{
    __shared__ float xs[128][36];     // 128 rows x 32 k (pad 36: conflict-free)
    __shared__ float wh[32][72];      // W-chunk hi (tf32 values; pad 72)
    __shared__ float wl[32][72];      // W-chunk lo
    __shared__ float sc_s[64], of_s[64];

    const int tid  = threadIdx.x;
    const int r0   = blockIdx.x * 128;
    const int warp = tid >> 5;
    const int lane = tid & 31;
    const int gid  = lane >> 2;       // 0..7
    const int tig  = lane & 3;        // 0..3
    const int wrow = warp * 32;       // warp covers rows wrow..wrow+31

    if (tid < 64) {
        float s = bg[tid] * rsqrtf(bv[tid] + BN_EPS);
        sc_s[tid] = s;
        of_s[tid] = (pb[tid] - bm[tid]) * s + bb[tid];
    }

    float acc[2][8][4];
#pragma unroll
    for (int t = 0; t < 2; t++)
#pragma unroll
        for (int nt = 0; nt < 8; nt++)
#pragma unroll
            for (int j = 0; j < 4; j++) acc[t][nt][j] = 0.f;

    for (int kc = 0; kc < IN_C; kc += 32) {
        __syncthreads();   // retire previous chunk's smem readers
        // load x chunk: 128 rows x 32 cols = 1024 float4 slots
#pragma unroll
        for (int i = 0; i < 8; i++) {
            int s = tid + i * 128;
            int row = s >> 3, c4 = (s & 7) * 4;
            int gr = r0 + row;
            float4 v = make_float4(0.f, 0.f, 0.f, 0.f);
            if (gr < N_NODES)
                v = *(const float4*)&x[(size_t)gr * IN_C + kc + c4];
            xs[row][c4+0] = v.x; xs[row][c4+1] = v.y;
            xs[row][c4+2] = v.z; xs[row][c4+3] = v.w;
        }
        // load W chunk (32 x 64) and split into tf32 hi/lo
#pragma unroll
        for (int i = 0; i < 4; i++) {
            int s = tid + i * 128;
            int row = s >> 4, c4 = (s & 15) * 4;
            float4 v = *(const float4*)&W[(size_t)(kc + row) * HID + c4];
            float4 h, l;
            h.x = __uint_as_float(cvt_tf32(v.x)); l.x = __uint_as_float(cvt_tf32(v.x - h.x));
            h.y = __uint_as_float(cvt_tf32(v.y)); l.y = __uint_as_float(cvt_tf32(v.y - h.y));
            h.z = __uint_as_float(cvt_tf32(v.z)); l.z = __uint_as_float(cvt_tf32(v.z - h.z));
            h.w = __uint_as_float(cvt_tf32(v.w)); l.w = __uint_as_float(cvt_tf32(v.w - h.w));
            *(float4*)&wh[row][c4] = h;
            *(float4*)&wl[row][c4] = l;
        }
        __syncthreads();
#pragma unroll
        for (int k8 = 0; k8 < 4; k8++) {
            const int klo = k8 * 8;
            unsigned ah[2][4], al[2][4];
#pragma unroll
            for (int t = 0; t < 2; t++) {
                int rb = wrow + t * 16;
                float af[4];
                af[0] = xs[rb + gid    ][klo + tig];
                af[1] = xs[rb + gid + 8][klo + tig];
                af[2] = xs[rb + gid    ][klo + tig + 4];
                af[3] = xs[rb + gid + 8][klo + tig + 4];
#pragma unroll
                for (int j = 0; j < 4; j++) {
                    ah[t][j] = cvt_tf32(af[j]);
                    al[t][j] = cvt_tf32(af[j] - __uint_as_float(ah[t][j]));
                }
            }
#pragma unroll
            for (int nt = 0; nt < 8; nt++) {
                unsigned bh0 = __float_as_uint(wh[klo + tig    ][nt * 8 + gid]);
                unsigned bh1 = __float_as_uint(wh[klo + tig + 4][nt * 8 + gid]);
                unsigned bl0 = __float_as_uint(wl[klo + tig    ][nt * 8 + gid]);
                unsigned bl1 = __float_as_uint(wl[klo + tig + 4][nt * 8 + gid]);
#pragma unroll
                for (int t = 0; t < 2; t++) {
                    mma_tf32(acc[t][nt], al[t], bh0, bh1);   // x_lo @ W_hi
                    mma_tf32(acc[t][nt], ah[t], bl0, bl1);   // x_hi @ W_lo
                    mma_tf32(acc[t][nt], ah[t], bh0, bh1);   // x_hi @ W_hi
                }
            }
        }
    }
    // epilogue: bn1 + elu
#pragma unroll
    for (int t = 0; t < 2; t++) {
        const int rtop = r0 + wrow + t * 16 + gid;
        const int rbot = rtop + 8;
#pragma unroll
        for (int nt = 0; nt < 8; nt++) {
            int c0 = nt * 8 + tig * 2;
            float s0 = sc_s[c0], s1 = sc_s[c0 + 1];
            float o0 = of_s[c0], o1 = of_s[c0 + 1];
            if (rtop < N_NODES) {
                float2 v = make_float2(elu1(acc[t][nt][0] * s0 + o0),
                                       elu1(acc[t][nt][1] * s1 + o1));
                *(float2*)&g_h[(size_t)rtop * HID + c0] = v;
            }
            if (rbot < N_NODES) {
                float2 v = make_float2(elu1(acc[t][nt][2] * s0 + o0),
                                       elu1(acc[t][nt][3] * s1 + o1));
                *(float2*)&g_h[(size_t)rbot * HID + c0] = v;
            }
        }
    }
}

// ---------------- K2: xw = g_h @ W1 (64x64), conv1 (H=8) -----------------
// FUSED: attention logits (per-row per-head, shfl-pair reduction) and
// zeroing of g_agg/g_denom for this block's rows. Replaces k_att<8,8>.
__global__ __launch_bounds__(128) void k_gemm64(
    const float* __restrict__ W,
    const float* __restrict__ att_s, const float* __restrict__ att_d)
{
    __shared__ float xs[64][65];
    __shared__ float ws[64][64];
    const int tid = threadIdx.x;
    const int r0 = blockIdx.x * 64;
    const int cg = tid & 15;
    const int rg = tid >> 4;
    u64 acc01[8], acc23[8];
#pragma unroll
    for (int i = 0; i < 8; i++) { acc01[i] = 0ull; acc23[i] = 0ull; }

#pragma unroll
    for (int i = 0; i < 8; i++) {
        int s = tid + i * 128;
        int row = s >> 4, c4 = (s & 15) * 4;
        float4 val = make_float4(0.f, 0.f, 0.f, 0.f);
        int gr = r0 + row;
        if (gr < N_NODES)
            val = *(const float4*)&g_h[(size_t)gr * HID + c4];
        xs[row][c4+0] = val.x; xs[row][c4+1] = val.y;
        xs[row][c4+2] = val.z; xs[row][c4+3] = val.w;
        *(float4*)&ws[row][c4] = *(const float4*)&W[(size_t)row * HID + c4];
    }
    __syncthreads();
    // zero agg/denom for conv1 (this block's rows; consumed by k_edge<8>)
#pragma unroll
    for (int i = 0; i < 8; i++) {
        int s = tid + i * 128;            // 1024 float4 = 64 rows x 16
        int row = s >> 4, cq = s & 15;
        int gr = r0 + row;
        if (gr < N_NODES)
            *(float4*)&g_agg[(size_t)gr * HID + cq * 4] =
                make_float4(0.f, 0.f, 0.f, 0.f);
    }
    {
        int row = tid >> 1, half = tid & 1;   // 128 float4 = 64 rows x 8 denoms
        int gr = r0 + row;
        if (gr < N_NODES)
            *(float4*)&g_denom[gr * 8 + half * 4] =
                make_float4(0.f, 0.f, 0.f, 0.f);
    }
#pragma unroll 8
    for (int k = 0; k < 64; k++) {
        float4 w = *(float4*)&ws[k][cg * 4];
        u64 w01 = pk2(w.x, w.y);
        u64 w23 = pk2(w.z, w.w);
#pragma unroll
        for (int i = 0; i < 8; i++) {
            float xv = xs[rg * 8 + i][k];
            u64 xx = pk2(xv, xv);
            fma2(acc01[i], xx, w01);
            fma2(acc23[i], xx, w23);
        }
    }
    const int c0 = cg * 4;
    const float4 as4 = *(const float4*)&att_s[c0];   // flat (8,8) == col index
    const float4 ad4 = *(const float4*)&att_d[c0];
    const int head = cg >> 1;                        // 4-col group is in one head
#pragma unroll
    for (int i = 0; i < 8; i++) {
        int gr = r0 + rg * 8 + i;
        float2 a01 = upk(acc01[i]);
        float2 a23 = upk(acc23[i]);
        if (gr < N_NODES) {
            *(float4*)&g_xw[(size_t)gr * HID + c0] =
                make_float4(a01.x, a01.y, a23.x, a23.y);
        }
        float ps = a01.x * as4.x + a01.y * as4.y + a23.x * as4.z + a23.y * as4.w;
        float pd = a01.x * ad4.x + a01.y * ad4.y + a23.x * ad4.z + a23.y * ad4.w;
        // pair lanes cg even/odd own one head; lanes differ only in bit 0
        ps += __shfl_xor_sync(0xffffffffu, ps, 1);
        pd += __shfl_xor_sync(0xffffffffu, pd, 1);
        if ((cg & 1) == 0 && gr < N_NODES) {
            g_asrc[gr * 8 + head] = ps;
            g_adst[gr * 8 + head] = pd;
        }
    }
}

// ---- K2b: conv2 GEMM (H=1) with FUSED conv1-post, attention logits, ----
// and agg/denom zeroing. Replaces k_post<8> + k_gemm64 + k_att<1,64>.
__global__ __launch_bounds__(128) void k_gemm64_post(
    const float* __restrict__ W,
    const float* __restrict__ bias,
    const float* __restrict__ bg, const float* __restrict__ bb,
    const float* __restrict__ bm, const float* __restrict__ bv,
    const float* __restrict__ att_s, const float* __restrict__ att_d)
{
    __shared__ float xs[64][65];
    __shared__ float ws[64][64];
    const int tid = threadIdx.x;
    const int r0 = blockIdx.x * 64;
    const int cg = tid & 15;
    const int rg = tid >> 4;
    u64 acc01[8], acc23[8];
#pragma unroll
    for (int i = 0; i < 8; i++) { acc01[i] = 0ull; acc23[i] = 0ull; }

#pragma unroll
    for (int i = 0; i < 8; i++) {
        int s = tid + i * 128;
        int row = s >> 4, c4 = (s & 15) * 4;
        int gr = r0 + row;
        float4 o = make_float4(0.f, 0.f, 0.f, 0.f);
        if (gr < N_NODES) {
            float4 a  = *(const float4*)&g_agg[(size_t)gr * HID + c4];
            float4 ho = *(const float4*)&g_h[(size_t)gr * HID + c4];
            float inv = 1.f / g_denom[gr * 8 + (c4 >> 3)];
            float av[4] = { a.x * inv, a.y * inv, a.z * inv, a.w * inv };
            float hv[4] = { ho.x, ho.y, ho.z, ho.w };
            float ov[4];
#pragma unroll
            for (int jj = 0; jj < 4; jj++) {
                int c = c4 + jj;
                float sfac = bg[c] * rsqrtf(bv[c] + BN_EPS);
                float t = (av[jj] + bias[c] - bm[c]) * sfac + bb[c] + hv[jj];
                ov[jj] = elu1(t);
            }
            o = make_float4(ov[0], ov[1], ov[2], ov[3]);
            *(float4*)&g_h[(size_t)gr * HID + c4] = o;   // conv2 identity
        }
        xs[row][c4+0] = o.x; xs[row][c4+1] = o.y;
        xs[row][c4+2] = o.z; xs[row][c4+3] = o.w;
        *(float4*)&ws[row][c4] = *(const float4*)&W[(size_t)row * HID + c4];
    }
    __syncthreads();
    // zero agg/denom for conv2 (AFTER the load stage above read conv1's agg)
#pragma unroll
    for (int i = 0; i < 8; i++) {
        int s = tid + i * 128;
        int row = s >> 4, cq = s & 15;
        int gr = r0 + row;
        if (gr < N_NODES)
            *(float4*)&g_agg[(size_t)gr * HID + cq * 4] =
                make_float4(0.f, 0.f, 0.f, 0.f);
    }
    if (tid < 64) {
        int gr = r0 + tid;
        if (gr < N_NODES) g_denom[gr] = 0.f;     // H=1
    }
#pragma unroll 8
    for (int k = 0; k < 64; k++) {
        float4 w = *(float4*)&ws[k][cg * 4];
        u64 w01 = pk2(w.x, w.y);
        u64 w23 = pk2(w.z, w.w);
#pragma unroll
        for (int i = 0; i < 8; i++) {
            float xv = xs[rg * 8 + i][k];
            u64 xx = pk2(xv, xv);
            fma2(acc01[i], xx, w01);
            fma2(acc23[i], xx, w23);
        }
    }
    const int c0 = cg * 4;
    const float4 as4 = *(const float4*)&att_s[c0];   // flat (1,64) == col index
    const float4 ad4 = *(const float4*)&att_d[c0];
#pragma unroll
    for (int i = 0; i < 8; i++) {
        int gr = r0 + rg * 8 + i;
        float2 a01 = upk(acc01[i]);
        float2 a23 = upk(acc23[i]);
        if (gr < N_NODES) {
            *(float4*)&g_xw[(size_t)gr * HID + c0] =
                make_float4(a01.x, a01.y, a23.x, a23.y);
        }
        float ps = a01.x * as4.x + a01.y * as4.y + a23.x * as4.z + a23.y * as4.w;
        float pd = a01.x * ad4.x + a01.y * ad4.y + a23.x * ad4.z + a23.y * ad4.w;
        // reduce across the 16 lanes (same rg) that own this row's 64 cols
#pragma unroll
        for (int off = 1; off < 16; off <<= 1) {
            ps += __shfl_xor_sync(0xffffffffu, ps, off);
            pd += __shfl_xor_sync(0xffffffffu, pd, off);
        }
        if (cg == 0 && gr < N_NODES) {
            g_asrc[gr] = ps;
            g_adst[gr] = pd;
        }
    }
}

// ---------------- K5: FUSED edge pass ----------------
// 8 threads per edge; lane j handles head j (H=8) / features j*8..j*8+7.
template<int H>
__global__ void k_edge(const int* __restrict__ ei)
{
    int t = blockIdx.x * blockDim.x + threadIdx.x;
    int j = t & 7;
    int e = t >> 3;
    if (e >= E_TOT) return;
    int src, dst;
    edge_decode(ei, e, src, dst);
    float ex;
    if (H == 8) {
        float a = g_asrc[src * 8 + j] + g_adst[dst * 8 + j];
        ex = expf(lrelu(a));
        atomicAdd(&g_denom[dst * 8 + j], ex);
    } else {
        float a = g_asrc[src] + g_adst[dst];
        ex = expf(lrelu(a));
        if (j == 0) atomicAdd(&g_denom[dst], ex);
    }
    const float4* xp = (const float4*)&g_xw[src * HID + j * 8];
    float4 a = xp[0], b = xp[1];
    a.x *= ex; a.y *= ex; a.z *= ex; a.w *= ex;
    b.x *= ex; b.y *= ex; b.z *= ex; b.w *= ex;
    atomicAddF4((float4*)&g_agg[dst * HID + j * 8], a);
    atomicAddF4((float4*)&g_agg[dst * HID + j * 8 + 4], b);
}

// ---------------- K7: classifier with FUSED conv2-post -------------------
__global__ __launch_bounds__(128) void k_cls_post(
    const float* __restrict__ W, const float* __restrict__ biasc,
    const float* __restrict__ bias2,
    const float* __restrict__ bg, const float* __restrict__ bb,
    const float* __restrict__ bm, const float* __restrict__ bv,
    float* __restrict__ out)
{
    __shared__ float hs[128][65];
    __shared__ float ws[64][8];
    const int tid = threadIdx.x;
    const int n0 = blockIdx.x * 128;
#pragma unroll
    for (int i = 0; i < 4; i++) {
        int s = tid + i * 128;
        ws[s >> 3][s & 7] = W[s];
    }
#pragma unroll
    for (int i = 0; i < 16; i++) {
        int s = tid + i * 128;            // float4 slot
        int row = s >> 4, c4 = (s & 15) * 4;
        int node = n0 + row;
        float4 o = make_float4(0.f, 0.f, 0.f, 0.f);
        if (node < N_NODES) {
            float4 a  = *(const float4*)&g_agg[(size_t)node * HID + c4];
            float4 ho = *(const float4*)&g_h[(size_t)node * HID + c4];
            float inv = 1.f / g_denom[node];          // H=1
            float av[4] = { a.x * inv, a.y * inv, a.z * inv, a.w * inv };
            float hv[4] = { ho.x, ho.y, ho.z, ho.w };
            float ov[4];
#pragma unroll
            for (int jj = 0; jj < 4; jj++) {
                int c = c4 + jj;
                float sfac = bg[c] * rsqrtf(bv[c] + BN_EPS);
                float t = (av[jj] + bias2[c] - bm[c]) * sfac + bb[c] + hv[jj];
                ov[jj] = elu1(t);
            }
            o = make_float4(ov[0], ov[1], ov[2], ov[3]);
        }
        hs[row][c4+0] = o.x; hs[row][c4+1] = o.y;
        hs[row][c4+2] = o.z; hs[row][c4+3] = o.w;
    }
    __syncthreads();
    if (n0 + tid >= N_NODES) return;
    float acc[8];
#pragma unroll
    for (int jj = 0; jj < 8; jj++) acc[jj] = biasc[jj];
#pragma unroll 8
    for (int k = 0; k < 64; k++) {
        float xv = hs[tid][k];
        float4 w0 = *(float4*)&ws[k][0];
        float4 w1 = *(float4*)&ws[k][4];
        acc[0] += xv * w0.x; acc[1] += xv * w0.y;
        acc[2] += xv * w0.z; acc[3] += xv * w0.w;
        acc[4] += xv * w1.x; acc[5] += xv * w1.y;
        acc[6] += xv * w1.z; acc[7] += xv * w1.w;
    }
    float* op = &out[(size_t)(n0 + tid) * 8];
    *(float4*)&op[0] = make_float4(acc[0], acc[1], acc[2], acc[3]);
    *(float4*)&op[4] = make_float4(acc[4], acc[5], acc[6], acc[7]);
}

// ---------------- launch ----------------
extern "C" void kernel_launch(void* const* d_in, const int* in_sizes, int n_in,
                              void* d_out, int out_size)
{
    const float* x        = (const float*)d_in[0];
    const int*   ei       = (const int*)  d_in[1];
    const float* proj_W   = (const float*)d_in[2];
    const float* proj_b   = (const float*)d_in[3];
    const float* bn1_g    = (const float*)d_in[4];
    const float* bn1_b    = (const float*)d_in[5];
    const float* bn1_m    = (const float*)d_in[6];
    const float* bn1_v    = (const float*)d_in[7];
    const float* bn2_g    = (const float*)d_in[8];
    const float* bn2_b    = (const float*)d_in[9];
    const float* bn2_m    = (const float*)d_in[10];
    const float* bn2_v    = (const float*)d_in[11];
    const float* bn3_g    = (const float*)d_in[12];
    const float* bn3_b    = (const float*)d_in[13];
    const float* bn3_m    = (const float*)d_in[14];
    const float* bn3_v    = (const float*)d_in[15];
    const float* W1       = (const float*)d_in[16];
    const float* att_src1 = (const float*)d_in[17];
    const float* att_dst1 = (const float*)d_in[18];
    const float* b1       = (const float*)d_in[19];
    const float* W2       = (const float*)d_in[20];
    const float* att_src2 = (const float*)d_in[21];
    const float* att_dst2 = (const float*)d_in[22];
    const float* b2       = (const float*)d_in[23];
    const float* cls_W    = (const float*)d_in[24];
    const float* cls_b    = (const float*)d_in[25];
    float* out = (float*)d_out;

    const int GEMM_IN_BLOCKS = (N_NODES + 127) / 128;         // 391
    const int GEMM_BLOCKS = (N_NODES + 63) / 64;              // 782
    const int EDGE_BLOCKS = (E_TOT * 8 + 255) / 256;          // 26563

    // projection + bn1 + elu (tf32 tensor cores, 3xTF32 compensated)
    k_gemm_in<<<GEMM_IN_BLOCKS, 128>>>(x, proj_W, proj_b, bn1_g, bn1_b, bn1_m, bn1_v);

    // ---- conv1 (H=8, C=8): GEMM + logits + zeroing fused ----
    k_gemm64<<<GEMM_BLOCKS, 128>>>(W1, att_src1, att_dst1);
    k_edge<8><<<EDGE_BLOCKS, 256>>>(ei);

    // ---- conv2 (H=1, C=64): conv1-post + GEMM + logits + zeroing fused ----
    k_gemm64_post<<<GEMM_BLOCKS, 128>>>(W2, b1, bn2_g, bn2_b, bn2_m, bn2_v,
                                        att_src2, att_dst2);
    k_edge<1><<<EDGE_BLOCKS, 256>>>(ei);

    // classifier; conv2-post fused into its load stage
    k_cls_post<<<(N_NODES + 127) / 128, 128>>>(cls_W, cls_b, b2,
                                               bn3_g, bn3_b, bn3_m, bn3_v, out);
}